// round 4
// baseline (speedup 1.0000x reference)
#include <cuda_runtime.h>
#include <cuda_bf16.h>
#include <math.h>

// ---------------- problem constants ----------------
#define BATCH   2
#define LSEQ    2048
#define DMODEL  512
#define DINNER  1024
#define DSTATE  16
#define DTRANK  32
#define DCONV   4
#define NROWS   (BATCH*LSEQ)          // 4096
#define XZCOLS  (2*DINNER)            // 2048
#define DBLCOLS (DTRANK + 2*DSTATE)   // 64

// ---------------- scratch (device globals; no allocation) ----------------
__device__ float g_xz [NROWS * XZCOLS];   // 32 MB : [xi | z]
__device__ float g_xc [NROWS * DINNER];   // 16 MB : conv+silu output
__device__ float g_dbl[NROWS * DBLCOLS];  //  1 MB : [dtr | B | C]
__device__ float g_dt [NROWS * DINNER];   // 16 MB : softplus(dt)
__device__ float g_y  [NROWS * DINNER];   // 16 MB : scan output (gated)
__device__ float g_o  [NROWS * DMODEL];   //  8 MB : pre-LN gemm output

// ---------------- generic fp32 tiled GEMM: C[MxN] = A[MxK] @ B[KxN] -----
// BM=BN=128, BK=16, 256 threads, 8x8 microtile. M%128==0, N%128==0, K%16==0.
__global__ __launch_bounds__(256) void sgemm_kernel(
    const float* __restrict__ A, const float* __restrict__ B,
    float* __restrict__ C, int M, int N, int K)
{
    __shared__ float As[16][129];   // padded: conflict-free transposed store
    __shared__ float Bs[16][128];

    const int tid = threadIdx.x;
    const int tx  = tid & 15;       // 0..15  (N direction)
    const int ty  = tid >> 4;       // 0..15  (M direction)
    const int bRowA = tid >> 2;           // 0..63
    const int cColA = (tid & 3) * 4;      // 0,4,8,12
    const int bRowB = tid >> 5;           // 0..7
    const int cColB = (tid & 31) * 4;     // 0..124

    const float* Ap = A + (size_t)(blockIdx.y * 128) * K;
    const float* Bp = B + blockIdx.x * 128;

    float acc[8][8];
    #pragma unroll
    for (int i = 0; i < 8; i++)
        #pragma unroll
        for (int j = 0; j < 8; j++) acc[i][j] = 0.f;

    for (int k0 = 0; k0 < K; k0 += 16) {
        #pragma unroll
        for (int i = 0; i < 2; i++) {
            int r = bRowA + i * 64;
            float4 v = *(const float4*)(Ap + (size_t)r * K + k0 + cColA);
            As[cColA + 0][r] = v.x; As[cColA + 1][r] = v.y;
            As[cColA + 2][r] = v.z; As[cColA + 3][r] = v.w;
        }
        #pragma unroll
        for (int i = 0; i < 2; i++) {
            int r = bRowB + i * 8;
            *(float4*)&Bs[r][cColB] =
                *(const float4*)(Bp + (size_t)(k0 + r) * N + cColB);
        }
        __syncthreads();
        #pragma unroll
        for (int kk = 0; kk < 16; kk++) {
            float a[8], b[8];
            #pragma unroll
            for (int i = 0; i < 8; i++) a[i] = As[kk][ty * 8 + i];
            #pragma unroll
            for (int j = 0; j < 8; j++) b[j] = Bs[kk][tx * 8 + j];
            #pragma unroll
            for (int i = 0; i < 8; i++)
                #pragma unroll
                for (int j = 0; j < 8; j++) acc[i][j] += a[i] * b[j];
        }
        __syncthreads();
    }

    float* Cp = C + (size_t)(blockIdx.y * 128 + ty * 8) * N + blockIdx.x * 128 + tx * 8;
    #pragma unroll
    for (int i = 0; i < 8; i++) {
        #pragma unroll
        for (int j = 0; j < 8; j += 4) {
            float4 v = make_float4(acc[i][j], acc[i][j+1], acc[i][j+2], acc[i][j+3]);
            *(float4*)(Cp + (size_t)i * N + j) = v;
        }
    }
}

// ---------------- depthwise causal conv (k=4) + bias + SiLU -------------
__global__ __launch_bounds__(256) void conv_silu_kernel(
    const float* __restrict__ xz, const float* __restrict__ cw,
    const float* __restrict__ cb, float* __restrict__ xc)
{
    int idx = blockIdx.x * 256 + threadIdx.x;       // over NROWS*DINNER
    if (idx >= NROWS * DINNER) return;
    int d   = idx & (DINNER - 1);
    int row = idx >> 10;
    int l   = row & (LSEQ - 1);
    int b   = row >> 11;

    float acc = cb[d];
    float4 w = *(const float4*)(cw + d * 4);
    const float* col = xz + (size_t)(b * LSEQ) * XZCOLS + d;
    if (l >= 3) {
        acc += col[(size_t)(l-3) * XZCOLS] * w.x;
        acc += col[(size_t)(l-2) * XZCOLS] * w.y;
        acc += col[(size_t)(l-1) * XZCOLS] * w.z;
        acc += col[(size_t)(l  ) * XZCOLS] * w.w;
    } else {
        const float wv[4] = {w.x, w.y, w.z, w.w};
        #pragma unroll
        for (int k = 0; k < 4; k++) {
            int ll = l - 3 + k;
            if (ll >= 0) acc += col[(size_t)ll * XZCOLS] * wv[k];
        }
    }
    float sig = 1.f / (1.f + __expf(-acc));
    xc[idx] = acc * sig;
}

// ---------------- dbl = xc @ W_xproj  (N=64, K=1024) --------------------
__global__ __launch_bounds__(256) void gemm_dbl_kernel(
    const float* __restrict__ X, const float* __restrict__ W,
    float* __restrict__ O)
{
    __shared__ float Xs[32][65];
    __shared__ float Ws[32][64];
    const int tid = threadIdx.x;
    const int tx = tid & 15, ty = tid >> 4;
    const int row0 = blockIdx.x * 64;

    float acc[4][4];
    #pragma unroll
    for (int i = 0; i < 4; i++)
        #pragma unroll
        for (int j = 0; j < 4; j++) acc[i][j] = 0.f;

    for (int k0 = 0; k0 < DINNER; k0 += 32) {
        #pragma unroll
        for (int i = 0; i < 2; i++) {
            int t = tid + i * 256;
            int r = t >> 3, c = (t & 7) * 4;
            float4 v = *(const float4*)(X + (size_t)(row0 + r) * DINNER + k0 + c);
            Xs[c+0][r] = v.x; Xs[c+1][r] = v.y; Xs[c+2][r] = v.z; Xs[c+3][r] = v.w;
        }
        #pragma unroll
        for (int i = 0; i < 2; i++) {
            int t = tid + i * 256;
            int r = t >> 4, c = (t & 15) * 4;
            *(float4*)&Ws[r][c] = *(const float4*)(W + (size_t)(k0 + r) * 64 + c);
        }
        __syncthreads();
        #pragma unroll
        for (int kk = 0; kk < 32; kk++) {
            float a[4], b[4];
            #pragma unroll
            for (int i = 0; i < 4; i++) a[i] = Xs[kk][ty*4+i];
            #pragma unroll
            for (int j = 0; j < 4; j++) b[j] = Ws[kk][tx*4+j];
            #pragma unroll
            for (int i = 0; i < 4; i++)
                #pragma unroll
                for (int j = 0; j < 4; j++) acc[i][j] += a[i]*b[j];
        }
        __syncthreads();
    }
    #pragma unroll
    for (int i = 0; i < 4; i++) {
        float4 v = make_float4(acc[i][0], acc[i][1], acc[i][2], acc[i][3]);
        *(float4*)(O + (size_t)(row0 + ty*4 + i) * 64 + tx*4) = v;
    }
}

// ---------------- dt = softplus(dtr @ W_dt + b_dt)  (K=32) --------------
// 8 rows per block; W_dt streamed once per block from L2.
__global__ __launch_bounds__(256) void dt_kernel(
    const float* __restrict__ dbl, const float* __restrict__ Wdt,
    const float* __restrict__ bdt, float* __restrict__ dt)
{
    __shared__ float dtr[8][32];
    const int tid = threadIdx.x;
    const int row0 = blockIdx.x * 8;
    {
        int r = tid >> 5, c = tid & 31;
        dtr[r][c] = dbl[(size_t)(row0 + r) * DBLCOLS + c];
    }
    __syncthreads();

    const int base = tid * 4;
    float4 bb = *(const float4*)(bdt + base);
    float acc[8][4];
    #pragma unroll
    for (int r = 0; r < 8; r++) {
        acc[r][0] = bb.x; acc[r][1] = bb.y; acc[r][2] = bb.z; acc[r][3] = bb.w;
    }
    #pragma unroll
    for (int k = 0; k < 32; k++) {
        float4 w = *(const float4*)(Wdt + (size_t)k * DINNER + base);
        #pragma unroll
        for (int r = 0; r < 8; r++) {
            float a = dtr[r][k];
            acc[r][0] += a * w.x; acc[r][1] += a * w.y;
            acc[r][2] += a * w.z; acc[r][3] += a * w.w;
        }
    }
    #pragma unroll
    for (int r = 0; r < 8; r++) {
        float o[4];
        #pragma unroll
        for (int j = 0; j < 4; j++) {
            float v = acc[r][j];
            o[j] = (v > 20.f) ? v : log1pf(__expf(v));
        }
        *(float4*)(dt + (size_t)(row0 + r) * DINNER + base) =
            make_float4(o[0], o[1], o[2], o[3]);
    }
}

// ---------------- selective scan + skip(D) + SiLU(z) gate ---------------
// lane layout: warp = 2 channels x 16 states. s = lane&15, half = lane>>4.
__global__ __launch_bounds__(128) void scan_kernel(
    const float* __restrict__ xz, const float* __restrict__ xc,
    const float* __restrict__ dbl, const float* __restrict__ dt,
    const float* __restrict__ A_log, const float* __restrict__ Dp,
    float* __restrict__ y)
{
    const int gwarp = (blockIdx.x * blockDim.x + threadIdx.x) >> 5;
    const int lane  = threadIdx.x & 31;
    const int s     = lane & 15;
    const int half  = lane >> 4;
    const int ch    = gwarp * 2 + half;        // 0 .. BATCH*DINNER-1
    const int b     = ch >> 10;
    const int d     = ch & (DINNER - 1);

    const float A  = -__expf(A_log[d * DSTATE + s]);
    const float Dd = Dp[d];
    float h = 0.f;

    const size_t rowbase = (size_t)b * LSEQ;
    #pragma unroll 2
    for (int l = 0; l < LSEQ; l++) {
        const size_t row = rowbase + l;
        float dtv = dt[row * DINNER + d];
        float xv  = xc[row * DINNER + d];
        float Bv  = dbl[row * DBLCOLS + DTRANK + s];
        float Cv  = dbl[row * DBLCOLS + DTRANK + DSTATE + s];

        h = h * __expf(dtv * A) + dtv * xv * Bv;
        float p = h * Cv;
        p += __shfl_xor_sync(0xffffffffu, p, 8);
        p += __shfl_xor_sync(0xffffffffu, p, 4);
        p += __shfl_xor_sync(0xffffffffu, p, 2);
        p += __shfl_xor_sync(0xffffffffu, p, 1);
        if (s == 0) {
            float zv  = xz[row * XZCOLS + DINNER + d];
            float sig = 1.f / (1.f + __expf(-zv));
            y[row * DINNER + d] = (p + xv * Dd) * (zv * sig);
        }
    }
}

// ---------------- residual + LayerNorm ----------------------------------
__global__ __launch_bounds__(128) void ln_kernel(
    const float* __restrict__ go, const float* __restrict__ x,
    const float* __restrict__ gamma, const float* __restrict__ beta,
    float* __restrict__ out)
{
    const int row = blockIdx.x;
    const int tid = threadIdx.x;          // 128, 4 elems each
    float4 a  = *(const float4*)(go + (size_t)row * DMODEL + tid * 4);
    float4 xr = *(const float4*)(x  + (size_t)row * DMODEL + tid * 4);
    float v0 = a.x + xr.x, v1 = a.y + xr.y, v2 = a.z + xr.z, v3 = a.w + xr.w;

    float s  = v0 + v1 + v2 + v3;
    float sq = v0*v0 + v1*v1 + v2*v2 + v3*v3;
    #pragma unroll
    for (int o = 16; o > 0; o >>= 1) {
        s  += __shfl_xor_sync(0xffffffffu, s,  o);
        sq += __shfl_xor_sync(0xffffffffu, sq, o);
    }
    __shared__ float ss[4], ssq[4];
    if ((tid & 31) == 0) { ss[tid >> 5] = s; ssq[tid >> 5] = sq; }
    __syncthreads();
    s  = ss[0]  + ss[1]  + ss[2]  + ss[3];
    sq = ssq[0] + ssq[1] + ssq[2] + ssq[3];

    const float mu  = s * (1.f / DMODEL);
    const float var = sq * (1.f / DMODEL) - mu * mu;
    const float inv = rsqrtf(var + 1e-5f);

    float4 g  = *(const float4*)(gamma + tid * 4);
    float4 be = *(const float4*)(beta  + tid * 4);
    float4 o;
    o.x = (v0 - mu) * inv * g.x + be.x;
    o.y = (v1 - mu) * inv * g.y + be.y;
    o.z = (v2 - mu) * inv * g.z + be.z;
    o.w = (v3 - mu) * inv * g.w + be.w;
    *(float4*)(out + (size_t)row * DMODEL + tid * 4) = o;
}

// ---------------- launcher ----------------------------------------------
extern "C" void kernel_launch(void* const* d_in, const int* in_sizes, int n_in,
                              void* d_out, int out_size)
{
    (void)in_sizes; (void)n_in; (void)out_size;
    const float* x      = (const float*)d_in[0];
    const float* W_in   = (const float*)d_in[1];
    const float* conv_w = (const float*)d_in[2];
    const float* conv_b = (const float*)d_in[3];
    const float* W_xprj = (const float*)d_in[4];
    const float* W_dt   = (const float*)d_in[5];
    const float* b_dt   = (const float*)d_in[6];
    const float* A_log  = (const float*)d_in[7];
    const float* Dvec   = (const float*)d_in[8];
    const float* W_out  = (const float*)d_in[9];
    const float* gamma  = (const float*)d_in[10];
    const float* beta   = (const float*)d_in[11];
    float* out = (float*)d_out;

    float *p_xz, *p_xc, *p_dbl, *p_dt, *p_y, *p_o;
    cudaGetSymbolAddress((void**)&p_xz,  g_xz);
    cudaGetSymbolAddress((void**)&p_xc,  g_xc);
    cudaGetSymbolAddress((void**)&p_dbl, g_dbl);
    cudaGetSymbolAddress((void**)&p_dt,  g_dt);
    cudaGetSymbolAddress((void**)&p_y,   g_y);
    cudaGetSymbolAddress((void**)&p_o,   g_o);

    // 1) xz = x @ W_in                       (4096x2048, K=512)
    sgemm_kernel<<<dim3(XZCOLS/128, NROWS/128), 256>>>(x, W_in, p_xz, NROWS, XZCOLS, DMODEL);
    // 2) xc = silu(causal_conv(xi) + b)
    conv_silu_kernel<<<(NROWS*DINNER)/256, 256>>>(p_xz, conv_w, conv_b, p_xc);
    // 3) dbl = xc @ W_xproj                  (4096x64, K=1024)
    gemm_dbl_kernel<<<NROWS/64, 256>>>(p_xc, W_xprj, p_dbl);
    // 4) dt = softplus(dtr @ W_dt + b_dt)    (4096x1024, K=32)
    dt_kernel<<<NROWS/8, 256>>>(p_dbl, W_dt, b_dt, p_dt);
    // 5) selective scan + D skip + silu(z) gate
    scan_kernel<<<(BATCH*DINNER/2)/4, 128>>>(p_xz, p_xc, p_dbl, p_dt, A_log, Dvec, p_y);
    // 6) o = y @ W_out                       (4096x512, K=1024)
    sgemm_kernel<<<dim3(DMODEL/128, NROWS/128), 256>>>(p_y, W_out, p_o, NROWS, DMODEL, DINNER);
    // 7) out = LN(o + x) * gamma + beta
    ln_kernel<<<NROWS, 128>>>(p_o, x, gamma, beta, out);
}

// round 7
// speedup vs baseline: 3.9382x; 3.9382x over previous
#include <cuda_runtime.h>
#include <cuda_bf16.h>
#include <math.h>

// ---------------- problem constants ----------------
#define BATCH   2
#define LSEQ    2048
#define DMODEL  512
#define DINNER  1024
#define DSTATE  16
#define DTRANK  32
#define NROWS   (BATCH*LSEQ)          // 4096
#define XZCOLS  (2*DINNER)            // 2048
#define DBLCOLS (DTRANK + 2*DSTATE)   // 64

// ---------------- scratch (device globals; no allocation) ----------------
__device__ float g_xz [NROWS * XZCOLS];   // [xi | z]
__device__ float g_xc [NROWS * DINNER];   // conv+silu output
__device__ float g_dbl[NROWS * DBLCOLS];  // [dtr | B | C]
__device__ float g_dt [NROWS * DINNER];   // softplus(dt)
__device__ float g_y  [NROWS * DINNER];   // scan output (gated)
__device__ float g_o  [NROWS * DMODEL];   // pre-LN gemm output

// ---------------- cp.async helpers ----------------
__device__ __forceinline__ void cp16(void* dst, const void* src) {
    unsigned u = (unsigned)__cvta_generic_to_shared(dst);
    asm volatile("cp.async.cg.shared.global [%0], [%1], 16;\n" :: "r"(u), "l"(src));
}

// ---------------- pipelined fp32 tiled GEMM: C[MxN] = A[MxK] @ B[KxN] ----
// BM=BN=128, BK=16, 256 threads, 8x8 microtile, double-buffered smem with
// register prefetch of the next k-tile. M%128==0, N%128==0, K%16==0.
__global__ __launch_bounds__(256) void sgemm_kernel(
    const float* __restrict__ A, const float* __restrict__ B,
    float* __restrict__ C, int M, int N, int K)
{
    __shared__ float As[2][16][129];
    __shared__ float Bs[2][16][128];

    const int tid = threadIdx.x;
    const int tx  = tid & 15;
    const int ty  = tid >> 4;
    const int bRowA = tid >> 2;           // 0..63
    const int cColA = (tid & 3) * 4;      // 0,4,8,12
    const int bRowB = tid >> 5;           // 0..7
    const int cColB = (tid & 31) * 4;     // 0..124

    const float* Ap = A + (size_t)(blockIdx.y * 128) * K;
    const float* Bp = B + blockIdx.x * 128;

    float acc[8][8];
    #pragma unroll
    for (int i = 0; i < 8; i++)
        #pragma unroll
        for (int j = 0; j < 8; j++) acc[i][j] = 0.f;

    float4 ra0, ra1, rb0, rb1;

    // load tile 0
    ra0 = *(const float4*)(Ap + (size_t)bRowA * K + cColA);
    ra1 = *(const float4*)(Ap + (size_t)(bRowA + 64) * K + cColA);
    rb0 = *(const float4*)(Bp + (size_t)bRowB * N + cColB);
    rb1 = *(const float4*)(Bp + (size_t)(bRowB + 8) * N + cColB);
    As[0][cColA+0][bRowA] = ra0.x; As[0][cColA+1][bRowA] = ra0.y;
    As[0][cColA+2][bRowA] = ra0.z; As[0][cColA+3][bRowA] = ra0.w;
    As[0][cColA+0][bRowA+64] = ra1.x; As[0][cColA+1][bRowA+64] = ra1.y;
    As[0][cColA+2][bRowA+64] = ra1.z; As[0][cColA+3][bRowA+64] = ra1.w;
    *(float4*)&Bs[0][bRowB][cColB] = rb0;
    *(float4*)&Bs[0][bRowB+8][cColB] = rb1;
    __syncthreads();

    const int ntiles = K >> 4;
    int p = 0;
    for (int kt = 0; kt < ntiles; kt++) {
        if (kt + 1 < ntiles) {
            const int k0 = (kt + 1) * 16;
            ra0 = *(const float4*)(Ap + (size_t)bRowA * K + k0 + cColA);
            ra1 = *(const float4*)(Ap + (size_t)(bRowA + 64) * K + k0 + cColA);
            rb0 = *(const float4*)(Bp + (size_t)(k0 + bRowB) * N + cColB);
            rb1 = *(const float4*)(Bp + (size_t)(k0 + bRowB + 8) * N + cColB);
        }
        #pragma unroll
        for (int kk = 0; kk < 16; kk++) {
            float a[8], b[8];
            #pragma unroll
            for (int i = 0; i < 8; i++) a[i] = As[p][kk][ty * 8 + i];
            #pragma unroll
            for (int j = 0; j < 8; j++) b[j] = Bs[p][kk][tx * 8 + j];
            #pragma unroll
            for (int i = 0; i < 8; i++)
                #pragma unroll
                for (int j = 0; j < 8; j++) acc[i][j] += a[i] * b[j];
        }
        if (kt + 1 < ntiles) {
            const int q = p ^ 1;
            As[q][cColA+0][bRowA] = ra0.x; As[q][cColA+1][bRowA] = ra0.y;
            As[q][cColA+2][bRowA] = ra0.z; As[q][cColA+3][bRowA] = ra0.w;
            As[q][cColA+0][bRowA+64] = ra1.x; As[q][cColA+1][bRowA+64] = ra1.y;
            As[q][cColA+2][bRowA+64] = ra1.z; As[q][cColA+3][bRowA+64] = ra1.w;
            *(float4*)&Bs[q][bRowB][cColB] = rb0;
            *(float4*)&Bs[q][bRowB+8][cColB] = rb1;
        }
        __syncthreads();
        p ^= 1;
    }

    float* Cp = C + (size_t)(blockIdx.y * 128 + ty * 8) * N + blockIdx.x * 128 + tx * 8;
    #pragma unroll
    for (int i = 0; i < 8; i++) {
        #pragma unroll
        for (int j = 0; j < 8; j += 4) {
            float4 v = make_float4(acc[i][j], acc[i][j+1], acc[i][j+2], acc[i][j+3]);
            *(float4*)(Cp + (size_t)i * N + j) = v;
        }
    }
}

// ---------------- depthwise causal conv (k=4) + bias + SiLU -------------
__global__ __launch_bounds__(256) void conv_silu_kernel(
    const float* __restrict__ xz, const float* __restrict__ cw,
    const float* __restrict__ cb, float* __restrict__ xc)
{
    int idx = blockIdx.x * 256 + threadIdx.x;
    if (idx >= NROWS * DINNER) return;
    int d   = idx & (DINNER - 1);
    int row = idx >> 10;
    int l   = row & (LSEQ - 1);
    int b   = row >> 11;

    float acc = cb[d];
    float4 w = *(const float4*)(cw + d * 4);
    const float* col = xz + (size_t)(b * LSEQ) * XZCOLS + d;
    if (l >= 3) {
        acc += col[(size_t)(l-3) * XZCOLS] * w.x;
        acc += col[(size_t)(l-2) * XZCOLS] * w.y;
        acc += col[(size_t)(l-1) * XZCOLS] * w.z;
        acc += col[(size_t)(l  ) * XZCOLS] * w.w;
    } else {
        const float wv[4] = {w.x, w.y, w.z, w.w};
        #pragma unroll
        for (int k = 0; k < 4; k++) {
            int ll = l - 3 + k;
            if (ll >= 0) acc += col[(size_t)ll * XZCOLS] * wv[k];
        }
    }
    float sig = 1.f / (1.f + __expf(-acc));
    xc[idx] = acc * sig;
}

// ---------------- dbl = xc @ W_xproj  (N=64, K=1024), 32 rows/block -----
__global__ __launch_bounds__(256) void gemm_dbl_kernel(
    const float* __restrict__ X, const float* __restrict__ W,
    float* __restrict__ O)
{
    __shared__ float Xs[32][33];
    __shared__ float Ws[32][64];
    const int tid = threadIdx.x;
    const int tx = tid & 15, ty = tid >> 4;       // ty: 2 rows, tx: 4 cols
    const int row0 = blockIdx.x * 32;
    const int rX = tid >> 3, cX = (tid & 7) * 4;

    float acc[2][4];
    #pragma unroll
    for (int i = 0; i < 2; i++)
        #pragma unroll
        for (int j = 0; j < 4; j++) acc[i][j] = 0.f;

    for (int k0 = 0; k0 < DINNER; k0 += 32) {
        float4 v = *(const float4*)(X + (size_t)(row0 + rX) * DINNER + k0 + cX);
        Xs[cX+0][rX] = v.x; Xs[cX+1][rX] = v.y;
        Xs[cX+2][rX] = v.z; Xs[cX+3][rX] = v.w;
        #pragma unroll
        for (int j = 0; j < 2; j++) {
            int t = tid + j * 256;
            int r = t >> 4, cc = (t & 15) * 4;
            *(float4*)&Ws[r][cc] = *(const float4*)(W + (size_t)(k0 + r) * 64 + cc);
        }
        __syncthreads();
        #pragma unroll
        for (int kk = 0; kk < 32; kk++) {
            float a0 = Xs[kk][ty*2+0];
            float a1 = Xs[kk][ty*2+1];
            float b0 = Ws[kk][tx*4+0], b1 = Ws[kk][tx*4+1];
            float b2 = Ws[kk][tx*4+2], b3 = Ws[kk][tx*4+3];
            acc[0][0] += a0*b0; acc[0][1] += a0*b1; acc[0][2] += a0*b2; acc[0][3] += a0*b3;
            acc[1][0] += a1*b0; acc[1][1] += a1*b1; acc[1][2] += a1*b2; acc[1][3] += a1*b3;
        }
        __syncthreads();
    }
    #pragma unroll
    for (int i = 0; i < 2; i++) {
        float4 v = make_float4(acc[i][0], acc[i][1], acc[i][2], acc[i][3]);
        *(float4*)(O + (size_t)(row0 + ty*2 + i) * 64 + tx*4) = v;
    }
}

// ---------------- dt = softplus(dtr @ W_dt + b_dt)  (K=32) --------------
__global__ __launch_bounds__(256) void dt_kernel(
    const float* __restrict__ dbl, const float* __restrict__ Wdt,
    const float* __restrict__ bdt, float* __restrict__ dt)
{
    __shared__ float dtr[8][32];
    const int tid = threadIdx.x;
    const int row0 = blockIdx.x * 8;
    {
        int r = tid >> 5, c = tid & 31;
        dtr[r][c] = dbl[(size_t)(row0 + r) * DBLCOLS + c];
    }
    __syncthreads();

    const int base = tid * 4;
    float4 bb = *(const float4*)(bdt + base);
    float acc[8][4];
    #pragma unroll
    for (int r = 0; r < 8; r++) {
        acc[r][0] = bb.x; acc[r][1] = bb.y; acc[r][2] = bb.z; acc[r][3] = bb.w;
    }
    #pragma unroll
    for (int k = 0; k < 32; k++) {
        float4 w = *(const float4*)(Wdt + (size_t)k * DINNER + base);
        #pragma unroll
        for (int r = 0; r < 8; r++) {
            float a = dtr[r][k];
            acc[r][0] += a * w.x; acc[r][1] += a * w.y;
            acc[r][2] += a * w.z; acc[r][3] += a * w.w;
        }
    }
    #pragma unroll
    for (int r = 0; r < 8; r++) {
        float o[4];
        #pragma unroll
        for (int j = 0; j < 4; j++) {
            float v = acc[r][j];
            o[j] = (v > 20.f) ? v : log1pf(__expf(v));
        }
        *(float4*)(dt + (size_t)(row0 + r) * DINNER + base) =
            make_float4(o[0], o[1], o[2], o[3]);
    }
}

// ---------------- selective scan v2: smem-staged + cp.async pipeline ----
// Block: 128 threads = 4 warps = 8 channels (warp = 2 ch x 16 states).
// Chunks of 64 timesteps double-buffered in shared memory.
#define SCH 8
#define ST  64
#define NCHUNK (LSEQ/ST)

struct ScanBuf {
    float dt[ST][SCH];
    float xc[ST][SCH];
    float zz[ST][SCH];
    float bc[ST][2*DSTATE];
};

__global__ __launch_bounds__(128) void scan_kernel(
    const float* __restrict__ xz, const float* __restrict__ xc,
    const float* __restrict__ dbl, const float* __restrict__ dt,
    const float* __restrict__ A_log, const float* __restrict__ Dp,
    float* __restrict__ y)
{
    __shared__ ScanBuf sb[2];
    __shared__ float sy[ST][SCH];

    const int tid  = threadIdx.x;
    const int lane = tid & 31;
    const int w    = tid >> 5;
    const int half = lane >> 4;
    const int s    = lane & 15;
    const int cl   = w * 2 + half;            // 0..7 local channel
    const int chb  = blockIdx.x * SCH;        // global channel base
    const int b    = chb >> 10;
    const int d0   = chb & (DINNER - 1);
    const int d    = d0 + cl;
    const size_t rowb = (size_t)b * LSEQ;

    const float A  = -__expf(A_log[d * DSTATE + s]);
    const float Dd = Dp[d];

    // staging thread mapping (used by both prefetch and flush)
    const int tq  = tid >> 1;                 // 0..63 : timestep
    const int qc  = (tid & 1) * 4;            // 0 or 4 : channel quad

    auto prefetch = [&](int c, int pp) {
        const size_t r0 = rowb + (size_t)c * ST;
        cp16(&sb[pp].dt[tq][qc], dt + (r0 + tq) * DINNER + d0 + qc);
        cp16(&sb[pp].xc[tq][qc], xc + (r0 + tq) * DINNER + d0 + qc);
        cp16(&sb[pp].zz[tq][qc], xz + (r0 + tq) * XZCOLS + DINNER + d0 + qc);
        #pragma unroll
        for (int j = 0; j < 4; j++) {
            int e = tid + j * 128;
            int tt = e >> 3, qq = (e & 7) * 4;
            cp16(&sb[pp].bc[tt][qq], dbl + (r0 + tt) * DBLCOLS + DTRANK + qq);
        }
        asm volatile("cp.async.commit_group;\n" ::);
    };

    prefetch(0, 0);
    prefetch(1, 1);

    float h = 0.f;
    for (int c = 0; c < NCHUNK; c++) {
        const int p = c & 1;
        if (c < NCHUNK - 1) asm volatile("cp.async.wait_group 1;\n" ::);
        else                asm volatile("cp.async.wait_group 0;\n" ::);
        __syncthreads();

        #pragma unroll 4
        for (int t = 0; t < ST; t++) {
            float dtv = sb[p].dt[t][cl];
            float xv  = sb[p].xc[t][cl];
            float Bv  = sb[p].bc[t][s];
            float Cv  = sb[p].bc[t][DSTATE + s];
            float e   = __expf(dtv * A);
            h = h * e + dtv * xv * Bv;
            float pr = h * Cv;
            pr += __shfl_xor_sync(0xffffffffu, pr, 8);
            pr += __shfl_xor_sync(0xffffffffu, pr, 4);
            pr += __shfl_xor_sync(0xffffffffu, pr, 2);
            pr += __shfl_xor_sync(0xffffffffu, pr, 1);
            if (s == 0) sy[t][cl] = pr + xv * Dd;
        }
        __syncthreads();

        // flush: read sy + z (own slice) BEFORE reusing buffer p for prefetch
        float4 yv = *(float4*)&sy[tq][qc];
        float4 zv = *(float4*)&sb[p].zz[tq][qc];
        if (c + 2 < NCHUNK) prefetch(c + 2, p);

        float4 o;
        o.x = yv.x * (zv.x / (1.f + __expf(-zv.x)));
        o.y = yv.y * (zv.y / (1.f + __expf(-zv.y)));
        o.z = yv.z * (zv.z / (1.f + __expf(-zv.z)));
        o.w = yv.w * (zv.w / (1.f + __expf(-zv.w)));
        const size_t r0 = rowb + (size_t)c * ST;
        *(float4*)(y + (r0 + tq) * DINNER + d0 + qc) = o;
    }
}

// ---------------- residual + LayerNorm ----------------------------------
__global__ __launch_bounds__(128) void ln_kernel(
    const float* __restrict__ go, const float* __restrict__ x,
    const float* __restrict__ gamma, const float* __restrict__ beta,
    float* __restrict__ out)
{
    const int row = blockIdx.x;
    const int tid = threadIdx.x;
    float4 a  = *(const float4*)(go + (size_t)row * DMODEL + tid * 4);
    float4 xr = *(const float4*)(x  + (size_t)row * DMODEL + tid * 4);
    float v0 = a.x + xr.x, v1 = a.y + xr.y, v2 = a.z + xr.z, v3 = a.w + xr.w;

    float s  = v0 + v1 + v2 + v3;
    float sq = v0*v0 + v1*v1 + v2*v2 + v3*v3;
    #pragma unroll
    for (int o = 16; o > 0; o >>= 1) {
        s  += __shfl_xor_sync(0xffffffffu, s,  o);
        sq += __shfl_xor_sync(0xffffffffu, sq, o);
    }
    __shared__ float ss[4], ssq[4];
    if ((tid & 31) == 0) { ss[tid >> 5] = s; ssq[tid >> 5] = sq; }
    __syncthreads();
    s  = ss[0]  + ss[1]  + ss[2]  + ss[3];
    sq = ssq[0] + ssq[1] + ssq[2] + ssq[3];

    const float mu  = s * (1.f / DMODEL);
    const float var = sq * (1.f / DMODEL) - mu * mu;
    const float inv = rsqrtf(var + 1e-5f);

    float4 g  = *(const float4*)(gamma + tid * 4);
    float4 be = *(const float4*)(beta  + tid * 4);
    float4 o;
    o.x = (v0 - mu) * inv * g.x + be.x;
    o.y = (v1 - mu) * inv * g.y + be.y;
    o.z = (v2 - mu) * inv * g.z + be.z;
    o.w = (v3 - mu) * inv * g.w + be.w;
    *(float4*)(out + (size_t)row * DMODEL + tid * 4) = o;
}

// ---------------- launcher ----------------------------------------------
extern "C" void kernel_launch(void* const* d_in, const int* in_sizes, int n_in,
                              void* d_out, int out_size)
{
    (void)in_sizes; (void)n_in; (void)out_size;
    const float* x      = (const float*)d_in[0];
    const float* W_in   = (const float*)d_in[1];
    const float* conv_w = (const float*)d_in[2];
    const float* conv_b = (const float*)d_in[3];
    const float* W_xprj = (const float*)d_in[4];
    const float* W_dt   = (const float*)d_in[5];
    const float* b_dt   = (const float*)d_in[6];
    const float* A_log  = (const float*)d_in[7];
    const float* Dvec   = (const float*)d_in[8];
    const float* W_out  = (const float*)d_in[9];
    const float* gamma  = (const float*)d_in[10];
    const float* beta   = (const float*)d_in[11];
    float* out = (float*)d_out;

    float *p_xz, *p_xc, *p_dbl, *p_dt, *p_y, *p_o;
    cudaGetSymbolAddress((void**)&p_xz,  g_xz);
    cudaGetSymbolAddress((void**)&p_xc,  g_xc);
    cudaGetSymbolAddress((void**)&p_dbl, g_dbl);
    cudaGetSymbolAddress((void**)&p_dt,  g_dt);
    cudaGetSymbolAddress((void**)&p_y,   g_y);
    cudaGetSymbolAddress((void**)&p_o,   g_o);

    // 1) xz = x @ W_in                       (4096x2048, K=512)
    sgemm_kernel<<<dim3(XZCOLS/128, NROWS/128), 256>>>(x, W_in, p_xz, NROWS, XZCOLS, DMODEL);
    // 2) xc = silu(causal_conv(xi) + b)
    conv_silu_kernel<<<(NROWS*DINNER)/256, 256>>>(p_xz, conv_w, conv_b, p_xc);
    // 3) dbl = xc @ W_xproj                  (4096x64, K=1024)
    gemm_dbl_kernel<<<NROWS/32, 256>>>(p_xc, W_xprj, p_dbl);
    // 4) dt = softplus(dtr @ W_dt + b_dt)    (4096x1024, K=32)
    dt_kernel<<<NROWS/8, 256>>>(p_dbl, W_dt, b_dt, p_dt);
    // 5) selective scan + D skip + silu(z) gate (smem-staged, double-buffered)
    scan_kernel<<<(BATCH*DINNER)/SCH, 128>>>(p_xz, p_xc, p_dbl, p_dt, A_log, Dvec, p_y);
    // 6) o = y @ W_out                       (4096x512, K=1024)
    sgemm_kernel<<<dim3(DMODEL/128, NROWS/128), 256>>>(p_y, W_out, p_o, NROWS, DMODEL, DINNER);
    // 7) out = LN(o + x) * gamma + beta
    ln_kernel<<<NROWS, 128>>>(p_o, x, gamma, beta, out);
}

// round 10
// speedup vs baseline: 5.9317x; 1.5062x over previous
#include <cuda_runtime.h>
#include <cuda_bf16.h>
#include <math.h>
#include <stdint.h>

// ---------------- problem constants ----------------
#define BATCH   2
#define LSEQ    2048
#define DMODEL  512
#define DINNER  1024
#define DSTATE  16
#define DTRANK  32
#define NROWS   (BATCH*LSEQ)          // 4096
#define XZCOLS  (2*DINNER)            // 2048
#define DBLCOLS (DTRANK + 2*DSTATE)   // 64

// ---------------- scratch (device globals; no allocation) ----------------
__device__ float g_xz [NROWS * XZCOLS];    // [xi | z]
__device__ float g_xc [NROWS * DINNER];    // conv+silu output
__device__ float g_dbl[NROWS * DBLCOLS];   // [dtr | B | C]
__device__ float g_dt [NROWS * DINNER];    // softplus(dt)
__device__ float g_y  [NROWS * DINNER];    // scan output (gated)
__device__ float g_o  [NROWS * DMODEL];    // pre-LN gemm output

// ---------------- helpers ----------------
__device__ __forceinline__ uint32_t s2u(const void* p) {
    uint32_t a;
    asm("{ .reg .u64 t; cvta.to.shared.u64 t, %1; cvt.u32.u64 %0, t; }"
        : "=r"(a) : "l"(p));
    return a;
}
__device__ __forceinline__ void cp16(uint32_t dst, const void* src) {
    asm volatile("cp.async.cg.shared.global [%0], [%1], 16;\n" :: "r"(dst), "l"(src));
}
__device__ __forceinline__ uint32_t f2tf(float f) {
    uint32_t u;
    asm("cvt.rna.tf32.f32 %0, %1;" : "=r"(u) : "f"(f));
    return u;
}
__device__ __forceinline__ void mma8(float* c, const uint32_t* a, const uint32_t* b) {
    asm volatile(
        "mma.sync.aligned.m16n8k8.row.col.f32.tf32.tf32.f32 "
        "{%0,%1,%2,%3}, {%4,%5,%6,%7}, {%8,%9}, {%0,%1,%2,%3};"
        : "+f"(c[0]), "+f"(c[1]), "+f"(c[2]), "+f"(c[3])
        : "r"(a[0]), "r"(a[1]), "r"(a[2]), "r"(a[3]), "r"(b[0]), "r"(b[1]));
}

// ---------------- tf32 tensor-core GEMM: C[M,N] = A[M,K] @ B[K,N] -------
// Block tile 128x128x16, 256 thr / 8 warps (2M x 4N), warp tile 64x32.
// A staged [128][20] (tf32 bits, conflict-free frag loads), B staged
// [16][136] k-major straight from the row-major weight (no transpose).
// Double-buffered smem + register prefetch. M%128==0, N%128==0, K%16==0.
#define TGM 128
#define TGN 128

__global__ __launch_bounds__(256) void tmma_kernel(
    const float* __restrict__ A, const float* __restrict__ B,
    float* __restrict__ C, int M, int N, int K)
{
    __shared__ uint32_t As[2][128][20];
    __shared__ uint32_t Bs[2][16][136];

    const int tid  = threadIdx.x;
    const int wid  = tid >> 5, lane = tid & 31;
    const int gid  = lane >> 2, tig = lane & 3;
    const int wm   = wid & 1,  wn  = wid >> 1;     // 2 x 4 warp grid
    const int m0   = blockIdx.y * TGM, n0 = blockIdx.x * TGN;

    // staging mapping
    const int ra = tid >> 1, ca = (tid & 1) * 8;   // A: row, col-base (8 cols)
    const int rb = tid >> 5, cb = (tid & 31) * 4;  // B: k-row (+0/+8), 4 cols

    const float* Aptr = A + (size_t)(m0 + ra) * K + ca;
    const float* Bptr = B + (size_t)rb * N + n0 + cb;

    float acc[16][4];
    #pragma unroll
    for (int i = 0; i < 16; i++)
        #pragma unroll
        for (int j = 0; j < 4; j++) acc[i][j] = 0.f;

    float4 va0, va1, vb0, vb1;
    auto stage = [&](int q) {
        uint4 u0 = make_uint4(f2tf(va0.x), f2tf(va0.y), f2tf(va0.z), f2tf(va0.w));
        uint4 u1 = make_uint4(f2tf(va1.x), f2tf(va1.y), f2tf(va1.z), f2tf(va1.w));
        *(uint4*)&As[q][ra][ca]     = u0;
        *(uint4*)&As[q][ra][ca + 4] = u1;
        uint4 w0 = make_uint4(f2tf(vb0.x), f2tf(vb0.y), f2tf(vb0.z), f2tf(vb0.w));
        uint4 w1 = make_uint4(f2tf(vb1.x), f2tf(vb1.y), f2tf(vb1.z), f2tf(vb1.w));
        *(uint4*)&Bs[q][rb][cb]     = w0;
        *(uint4*)&Bs[q][rb + 8][cb] = w1;
    };

    // tile 0
    va0 = *(const float4*)(Aptr + 0);
    va1 = *(const float4*)(Aptr + 4);
    vb0 = *(const float4*)(Bptr);
    vb1 = *(const float4*)(Bptr + (size_t)8 * N);
    stage(0);
    __syncthreads();

    const int ntiles = K >> 4;
    int p = 0;
    for (int kt = 0; kt < ntiles; kt++) {
        if (kt + 1 < ntiles) {
            const int k1 = (kt + 1) * 16;
            va0 = *(const float4*)(Aptr + k1);
            va1 = *(const float4*)(Aptr + k1 + 4);
            vb0 = *(const float4*)(Bptr + (size_t)k1 * N);
            vb1 = *(const float4*)(Bptr + (size_t)(k1 + 8) * N);
        }
        #pragma unroll
        for (int k0 = 0; k0 < 16; k0 += 8) {
            uint32_t af[4][4], bf[4][2];
            #pragma unroll
            for (int i = 0; i < 4; i++) {
                const int mr = wm * 64 + i * 16 + gid;
                af[i][0] = As[p][mr    ][k0 + tig];
                af[i][1] = As[p][mr + 8][k0 + tig];
                af[i][2] = As[p][mr    ][k0 + tig + 4];
                af[i][3] = As[p][mr + 8][k0 + tig + 4];
            }
            #pragma unroll
            for (int j = 0; j < 4; j++) {
                const int nc = wn * 32 + j * 8 + gid;
                bf[j][0] = Bs[p][k0 + tig    ][nc];
                bf[j][1] = Bs[p][k0 + tig + 4][nc];
            }
            #pragma unroll
            for (int i = 0; i < 4; i++)
                #pragma unroll
                for (int j = 0; j < 4; j++)
                    mma8(acc[i * 4 + j], af[i], bf[j]);
        }
        if (kt + 1 < ntiles) stage(p ^ 1);
        __syncthreads();
        p ^= 1;
    }

    // epilogue
    #pragma unroll
    for (int i = 0; i < 4; i++) {
        const int row = m0 + wm * 64 + i * 16 + gid;
        #pragma unroll
        for (int j = 0; j < 4; j++) {
            const int col = n0 + wn * 32 + j * 8 + tig * 2;
            float* Cp = C + (size_t)row * N + col;
            *(float2*)Cp = make_float2(acc[i * 4 + j][0], acc[i * 4 + j][1]);
            *(float2*)(Cp + (size_t)8 * N) = make_float2(acc[i * 4 + j][2], acc[i * 4 + j][3]);
        }
    }
}

// ---------------- depthwise causal conv (k=4) + bias + SiLU -------------
__global__ __launch_bounds__(256) void conv_silu_kernel(
    const float* __restrict__ xz, const float* __restrict__ cw,
    const float* __restrict__ cb, float* __restrict__ xc)
{
    int idx = blockIdx.x * 256 + threadIdx.x;
    if (idx >= NROWS * DINNER) return;
    int d   = idx & (DINNER - 1);
    int row = idx >> 10;
    int l   = row & (LSEQ - 1);
    int b   = row >> 11;

    float acc = cb[d];
    float4 w = *(const float4*)(cw + d * 4);
    const float* col = xz + (size_t)(b * LSEQ) * XZCOLS + d;
    if (l >= 3) {
        acc += col[(size_t)(l-3) * XZCOLS] * w.x;
        acc += col[(size_t)(l-2) * XZCOLS] * w.y;
        acc += col[(size_t)(l-1) * XZCOLS] * w.z;
        acc += col[(size_t)(l  ) * XZCOLS] * w.w;
    } else {
        const float wv[4] = {w.x, w.y, w.z, w.w};
        #pragma unroll
        for (int k = 0; k < 4; k++) {
            int ll = l - 3 + k;
            if (ll >= 0) acc += col[(size_t)ll * XZCOLS] * wv[k];
        }
    }
    float sig = 1.f / (1.f + __expf(-acc));
    xc[idx] = acc * sig;
}

// ---------------- dbl = xc @ W_xproj  (N=64, K=1024), 32 rows/block -----
__global__ __launch_bounds__(256) void gemm_dbl_kernel(
    const float* __restrict__ X, const float* __restrict__ W,
    float* __restrict__ O)
{
    __shared__ float Xs[32][33];
    __shared__ float Ws[32][64];
    const int tid = threadIdx.x;
    const int tx = tid & 15, ty = tid >> 4;
    const int row0 = blockIdx.x * 32;
    const int rX = tid >> 3, cX = (tid & 7) * 4;

    float acc[2][4];
    #pragma unroll
    for (int i = 0; i < 2; i++)
        #pragma unroll
        for (int j = 0; j < 4; j++) acc[i][j] = 0.f;

    for (int k0 = 0; k0 < DINNER; k0 += 32) {
        float4 v = *(const float4*)(X + (size_t)(row0 + rX) * DINNER + k0 + cX);
        Xs[cX+0][rX] = v.x; Xs[cX+1][rX] = v.y;
        Xs[cX+2][rX] = v.z; Xs[cX+3][rX] = v.w;
        #pragma unroll
        for (int j = 0; j < 2; j++) {
            int t = tid + j * 256;
            int r = t >> 4, cc = (t & 15) * 4;
            *(float4*)&Ws[r][cc] = *(const float4*)(W + (size_t)(k0 + r) * 64 + cc);
        }
        __syncthreads();
        #pragma unroll
        for (int kk = 0; kk < 32; kk++) {
            float a0 = Xs[kk][ty*2+0];
            float a1 = Xs[kk][ty*2+1];
            float b0 = Ws[kk][tx*4+0], b1 = Ws[kk][tx*4+1];
            float b2 = Ws[kk][tx*4+2], b3 = Ws[kk][tx*4+3];
            acc[0][0] += a0*b0; acc[0][1] += a0*b1; acc[0][2] += a0*b2; acc[0][3] += a0*b3;
            acc[1][0] += a1*b0; acc[1][1] += a1*b1; acc[1][2] += a1*b2; acc[1][3] += a1*b3;
        }
        __syncthreads();
    }
    #pragma unroll
    for (int i = 0; i < 2; i++) {
        float4 v = make_float4(acc[i][0], acc[i][1], acc[i][2], acc[i][3]);
        *(float4*)(O + (size_t)(row0 + ty*2 + i) * 64 + tx*4) = v;
    }
}

// ---------------- dt = softplus(dtr @ W_dt + b_dt)  (K=32) --------------
__global__ __launch_bounds__(256) void dt_kernel(
    const float* __restrict__ dbl, const float* __restrict__ Wdt,
    const float* __restrict__ bdt, float* __restrict__ dt)
{
    __shared__ float dtr[8][32];
    const int tid = threadIdx.x;
    const int row0 = blockIdx.x * 8;
    {
        int r = tid >> 5, c = tid & 31;
        dtr[r][c] = dbl[(size_t)(row0 + r) * DBLCOLS + c];
    }
    __syncthreads();

    const int base = tid * 4;
    float4 bb = *(const float4*)(bdt + base);
    float acc[8][4];
    #pragma unroll
    for (int r = 0; r < 8; r++) {
        acc[r][0] = bb.x; acc[r][1] = bb.y; acc[r][2] = bb.z; acc[r][3] = bb.w;
    }
    #pragma unroll
    for (int k = 0; k < 32; k++) {
        float4 w = *(const float4*)(Wdt + (size_t)k * DINNER + base);
        #pragma unroll
        for (int r = 0; r < 8; r++) {
            float a = dtr[r][k];
            acc[r][0] += a * w.x; acc[r][1] += a * w.y;
            acc[r][2] += a * w.z; acc[r][3] += a * w.w;
        }
    }
    #pragma unroll
    for (int r = 0; r < 8; r++) {
        float o[4];
        #pragma unroll
        for (int j = 0; j < 4; j++) {
            float v = acc[r][j];
            o[j] = (v > 20.f) ? v : log1pf(__expf(v));
        }
        *(float4*)(dt + (size_t)(row0 + r) * DINNER + base) =
            make_float4(o[0], o[1], o[2], o[3]);
    }
}

// ---------------- selective scan: smem-staged + cp.async pipeline -------
#define SCH 8
#define ST  64
#define NCHUNK (LSEQ/ST)

struct ScanBuf {
    float dt[ST][SCH];
    float xc[ST][SCH];
    float zz[ST][SCH];
    float bc[ST][2*DSTATE];
};

__global__ __launch_bounds__(128) void scan_kernel(
    const float* __restrict__ xz, const float* __restrict__ xc,
    const float* __restrict__ dbl, const float* __restrict__ dt,
    const float* __restrict__ A_log, const float* __restrict__ Dp,
    float* __restrict__ y)
{
    __shared__ ScanBuf sb[2];
    __shared__ float sy[ST][SCH];

    const int tid  = threadIdx.x;
    const int lane = tid & 31;
    const int w    = tid >> 5;
    const int half = lane >> 4;
    const int s    = lane & 15;
    const int cl   = w * 2 + half;
    const int chb  = blockIdx.x * SCH;
    const int b    = chb >> 10;
    const int d0   = chb & (DINNER - 1);
    const int d    = d0 + cl;
    const size_t rowb = (size_t)b * LSEQ;

    const float A  = -__expf(A_log[d * DSTATE + s]);
    const float Dd = Dp[d];

    const int tq  = tid >> 1;
    const int qc  = (tid & 1) * 4;

    auto prefetch = [&](int c, int pp) {
        const size_t r0 = rowb + (size_t)c * ST;
        cp16(s2u(&sb[pp].dt[tq][qc]), dt + (r0 + tq) * DINNER + d0 + qc);
        cp16(s2u(&sb[pp].xc[tq][qc]), xc + (r0 + tq) * DINNER + d0 + qc);
        cp16(s2u(&sb[pp].zz[tq][qc]), xz + (r0 + tq) * XZCOLS + DINNER + d0 + qc);
        #pragma unroll
        for (int j = 0; j < 4; j++) {
            int e = tid + j * 128;
            int tt = e >> 3, qq = (e & 7) * 4;
            cp16(s2u(&sb[pp].bc[tt][qq]), dbl + (r0 + tt) * DBLCOLS + DTRANK + qq);
        }
        asm volatile("cp.async.commit_group;\n" ::);
    };

    prefetch(0, 0);
    prefetch(1, 1);

    float h = 0.f;
    for (int c = 0; c < NCHUNK; c++) {
        const int p = c & 1;
        if (c < NCHUNK - 1) asm volatile("cp.async.wait_group 1;\n" ::);
        else                asm volatile("cp.async.wait_group 0;\n" ::);
        __syncthreads();

        #pragma unroll 4
        for (int t = 0; t < ST; t++) {
            float dtv = sb[p].dt[t][cl];
            float xv  = sb[p].xc[t][cl];
            float Bv  = sb[p].bc[t][s];
            float Cv  = sb[p].bc[t][DSTATE + s];
            float e   = __expf(dtv * A);
            h = h * e + dtv * xv * Bv;
            float pr = h * Cv;
            pr += __shfl_xor_sync(0xffffffffu, pr, 8);
            pr += __shfl_xor_sync(0xffffffffu, pr, 4);
            pr += __shfl_xor_sync(0xffffffffu, pr, 2);
            pr += __shfl_xor_sync(0xffffffffu, pr, 1);
            if (s == 0) sy[t][cl] = pr + xv * Dd;
        }
        __syncthreads();

        float4 yv = *(float4*)&sy[tq][qc];
        float4 zv = *(float4*)&sb[p].zz[tq][qc];
        if (c + 2 < NCHUNK) prefetch(c + 2, p);

        float4 o;
        o.x = yv.x * (zv.x / (1.f + __expf(-zv.x)));
        o.y = yv.y * (zv.y / (1.f + __expf(-zv.y)));
        o.z = yv.z * (zv.z / (1.f + __expf(-zv.z)));
        o.w = yv.w * (zv.w / (1.f + __expf(-zv.w)));
        const size_t r0 = rowb + (size_t)c * ST;
        *(float4*)(y + (r0 + tq) * DINNER + d0 + qc) = o;
    }
}

// ---------------- residual + LayerNorm ----------------------------------
__global__ __launch_bounds__(128) void ln_kernel(
    const float* __restrict__ go, const float* __restrict__ x,
    const float* __restrict__ gamma, const float* __restrict__ beta,
    float* __restrict__ out)
{
    const int row = blockIdx.x;
    const int tid = threadIdx.x;
    float4 a  = *(const float4*)(go + (size_t)row * DMODEL + tid * 4);
    float4 xr = *(const float4*)(x  + (size_t)row * DMODEL + tid * 4);
    float v0 = a.x + xr.x, v1 = a.y + xr.y, v2 = a.z + xr.z, v3 = a.w + xr.w;

    float s  = v0 + v1 + v2 + v3;
    float sq = v0*v0 + v1*v1 + v2*v2 + v3*v3;
    #pragma unroll
    for (int o = 16; o > 0; o >>= 1) {
        s  += __shfl_xor_sync(0xffffffffu, s,  o);
        sq += __shfl_xor_sync(0xffffffffu, sq, o);
    }
    __shared__ float ss[4], ssq[4];
    if ((tid & 31) == 0) { ss[tid >> 5] = s; ssq[tid >> 5] = sq; }
    __syncthreads();
    s  = ss[0]  + ss[1]  + ss[2]  + ss[3];
    sq = ssq[0] + ssq[1] + ssq[2] + ssq[3];

    const float mu  = s * (1.f / DMODEL);
    const float var = sq * (1.f / DMODEL) - mu * mu;
    const float inv = rsqrtf(var + 1e-5f);

    float4 g  = *(const float4*)(gamma + tid * 4);
    float4 be = *(const float4*)(beta  + tid * 4);
    float4 o;
    o.x = (v0 - mu) * inv * g.x + be.x;
    o.y = (v1 - mu) * inv * g.y + be.y;
    o.z = (v2 - mu) * inv * g.z + be.z;
    o.w = (v3 - mu) * inv * g.w + be.w;
    *(float4*)(out + (size_t)row * DMODEL + tid * 4) = o;
}

// ---------------- launcher ----------------------------------------------
extern "C" void kernel_launch(void* const* d_in, const int* in_sizes, int n_in,
                              void* d_out, int out_size)
{
    (void)in_sizes; (void)n_in; (void)out_size;
    const float* x      = (const float*)d_in[0];
    const float* W_in   = (const float*)d_in[1];
    const float* conv_w = (const float*)d_in[2];
    const float* conv_b = (const float*)d_in[3];
    const float* W_xprj = (const float*)d_in[4];
    const float* W_dt   = (const float*)d_in[5];
    const float* b_dt   = (const float*)d_in[6];
    const float* A_log  = (const float*)d_in[7];
    const float* Dvec   = (const float*)d_in[8];
    const float* W_out  = (const float*)d_in[9];
    const float* gamma  = (const float*)d_in[10];
    const float* beta   = (const float*)d_in[11];
    float* out = (float*)d_out;

    float *p_xz, *p_xc, *p_dbl, *p_dt, *p_y, *p_o;
    cudaGetSymbolAddress((void**)&p_xz,  g_xz);
    cudaGetSymbolAddress((void**)&p_xc,  g_xc);
    cudaGetSymbolAddress((void**)&p_dbl, g_dbl);
    cudaGetSymbolAddress((void**)&p_dt,  g_dt);
    cudaGetSymbolAddress((void**)&p_y,   g_y);
    cudaGetSymbolAddress((void**)&p_o,   g_o);

    // 1) xz = x @ W_in   (tf32 mma.sync, 4096x2048, K=512)
    tmma_kernel<<<dim3(XZCOLS/TGN, NROWS/TGM), 256>>>(x, W_in, p_xz, NROWS, XZCOLS, DMODEL);
    // 2) xc = silu(causal_conv(xi) + b)
    conv_silu_kernel<<<(NROWS*DINNER)/256, 256>>>(p_xz, conv_w, conv_b, p_xc);
    // 3) dbl = xc @ W_xproj   (4096x64, K=1024)
    gemm_dbl_kernel<<<NROWS/32, 256>>>(p_xc, W_xprj, p_dbl);
    // 4) dt = softplus(dtr @ W_dt + b_dt)
    dt_kernel<<<NROWS/8, 256>>>(p_dbl, W_dt, b_dt, p_dt);
    // 5) selective scan + D skip + silu(z) gate
    scan_kernel<<<(BATCH*DINNER)/SCH, 128>>>(p_xz, p_xc, p_dbl, p_dt, A_log, Dvec, p_y);
    // 6) o = y @ W_out   (tf32 mma.sync, 4096x512, K=1024)
    tmma_kernel<<<dim3(DMODEL/TGN, NROWS/TGM), 256>>>(p_y, W_out, p_o, NROWS, DMODEL, DINNER);
    // 7) out = LN(o + x) * gamma + beta
    ln_kernel<<<NROWS, 128>>>(p_o, x, gamma, beta, out);
}

// round 11
// speedup vs baseline: 6.0799x; 1.0250x over previous
#include <cuda_runtime.h>
#include <cuda_bf16.h>
#include <math.h>
#include <stdint.h>

// ---------------- problem constants ----------------
#define BATCH   2
#define LSEQ    2048
#define DMODEL  512
#define DINNER  1024
#define DSTATE  16
#define DTRANK  32
#define NROWS   (BATCH*LSEQ)          // 4096
#define XZCOLS  (2*DINNER)            // 2048
#define DBLCOLS (DTRANK + 2*DSTATE)   // 64

// ---------------- scratch (device globals; no allocation) ----------------
__device__ float g_xz [NROWS * XZCOLS];    // [xi | z]
__device__ float g_xc [NROWS * DINNER];    // conv+silu output
__device__ float g_dbl[NROWS * DBLCOLS];   // [dtr | B | C]
__device__ float g_dt [NROWS * DINNER];    // softplus(dt)
__device__ float g_y  [NROWS * DINNER];    // scan output (gated)
__device__ float g_o  [NROWS * DMODEL];    // pre-LN gemm output

// ---------------- helpers ----------------
__device__ __forceinline__ uint32_t s2u(const void* p) {
    uint32_t a;
    asm("{ .reg .u64 t; cvta.to.shared.u64 t, %1; cvt.u32.u64 %0, t; }"
        : "=r"(a) : "l"(p));
    return a;
}
__device__ __forceinline__ void cp16(uint32_t dst, const void* src) {
    asm volatile("cp.async.cg.shared.global [%0], [%1], 16;\n" :: "r"(dst), "l"(src));
}
__device__ __forceinline__ uint32_t f2tf(float f) {
    uint32_t u;
    asm("cvt.rna.tf32.f32 %0, %1;" : "=r"(u) : "f"(f));
    return u;
}
__device__ __forceinline__ void mma8(float* c, const uint32_t* a, const uint32_t* b) {
    asm volatile(
        "mma.sync.aligned.m16n8k8.row.col.f32.tf32.tf32.f32 "
        "{%0,%1,%2,%3}, {%4,%5,%6,%7}, {%8,%9}, {%0,%1,%2,%3};"
        : "+f"(c[0]), "+f"(c[1]), "+f"(c[2]), "+f"(c[3])
        : "r"(a[0]), "r"(a[1]), "r"(a[2]), "r"(a[3]), "r"(b[0]), "r"(b[1]));
}

// ---------------- tf32 tensor-core GEMM: C[M,N] = A[M,K] @ B[K,N] -------
// Block tile 128x128x16, 256 thr / 8 warps (2M x 4N), warp tile 64x32.
// 3-stage cp.async pipeline (global->smem as fp32); fp32->tf32 cvt at
// fragment load (ALU, overlapped). A smem [128][20] (conflict-free),
// B smem [16][136] k-major from the row-major weight (no transpose).
#define TGM 128
#define TGN 128
#define NSTAGE 3

__global__ __launch_bounds__(256) void tmma_kernel(
    const float* __restrict__ A, const float* __restrict__ B,
    float* __restrict__ C, int M, int N, int K)
{
    __shared__ float As[NSTAGE][128][20];
    __shared__ float Bs[NSTAGE][16][136];

    const int tid  = threadIdx.x;
    const int wid  = tid >> 5, lane = tid & 31;
    const int gid  = lane >> 2, tig = lane & 3;
    const int wm   = wid & 1,  wn  = wid >> 1;     // 2 x 4 warp grid
    const int m0   = blockIdx.y * TGM, n0 = blockIdx.x * TGN;

    // staging mapping
    const int ra = tid >> 1, ca = (tid & 1) * 8;   // A: row, col-base (8 cols)
    const int rb = tid >> 5, cb = (tid & 31) * 4;  // B: k-row (+0/+8), 4 cols

    const float* Aptr = A + (size_t)(m0 + ra) * K + ca;
    const float* Bptr = B + (size_t)rb * N + n0 + cb;

    auto stage = [&](int s, int kt) {
        const int k0 = kt * 16;
        cp16(s2u(&As[s][ra][ca]),     Aptr + k0);
        cp16(s2u(&As[s][ra][ca + 4]), Aptr + k0 + 4);
        cp16(s2u(&Bs[s][rb][cb]),     Bptr + (size_t)k0 * N);
        cp16(s2u(&Bs[s][rb + 8][cb]), Bptr + (size_t)(k0 + 8) * N);
        asm volatile("cp.async.commit_group;\n" ::);
    };

    float acc[16][4];
    #pragma unroll
    for (int i = 0; i < 16; i++)
        #pragma unroll
        for (int j = 0; j < 4; j++) acc[i][j] = 0.f;

    const int ntiles = K >> 4;
    stage(0, 0);
    stage(1, 1);

    for (int kt = 0; kt < ntiles; kt++) {
        const int p = kt % NSTAGE;
        if (kt < ntiles - 1) asm volatile("cp.async.wait_group 1;\n" ::);
        else                 asm volatile("cp.async.wait_group 0;\n" ::);
        __syncthreads();
        if (kt + 2 < ntiles) stage((kt + 2) % NSTAGE, kt + 2);

        #pragma unroll
        for (int k0 = 0; k0 < 16; k0 += 8) {
            uint32_t af[4][4], bf[4][2];
            #pragma unroll
            for (int i = 0; i < 4; i++) {
                const int mr = wm * 64 + i * 16 + gid;
                af[i][0] = f2tf(As[p][mr    ][k0 + tig]);
                af[i][1] = f2tf(As[p][mr + 8][k0 + tig]);
                af[i][2] = f2tf(As[p][mr    ][k0 + tig + 4]);
                af[i][3] = f2tf(As[p][mr + 8][k0 + tig + 4]);
            }
            #pragma unroll
            for (int j = 0; j < 4; j++) {
                const int nc = wn * 32 + j * 8 + gid;
                bf[j][0] = f2tf(Bs[p][k0 + tig    ][nc]);
                bf[j][1] = f2tf(Bs[p][k0 + tig + 4][nc]);
            }
            #pragma unroll
            for (int i = 0; i < 4; i++)
                #pragma unroll
                for (int j = 0; j < 4; j++)
                    mma8(acc[i * 4 + j], af[i], bf[j]);
        }
        __syncthreads();
    }

    // epilogue
    #pragma unroll
    for (int i = 0; i < 4; i++) {
        const int row = m0 + wm * 64 + i * 16 + gid;
        #pragma unroll
        for (int j = 0; j < 4; j++) {
            const int col = n0 + wn * 32 + j * 8 + tig * 2;
            float* Cp = C + (size_t)row * N + col;
            *(float2*)Cp = make_float2(acc[i * 4 + j][0], acc[i * 4 + j][1]);
            *(float2*)(Cp + (size_t)8 * N) = make_float2(acc[i * 4 + j][2], acc[i * 4 + j][3]);
        }
    }
}

// ---------------- depthwise causal conv (k=4) + bias + SiLU -------------
__global__ __launch_bounds__(256) void conv_silu_kernel(
    const float* __restrict__ xz, const float* __restrict__ cw,
    const float* __restrict__ cb, float* __restrict__ xc)
{
    int idx = blockIdx.x * 256 + threadIdx.x;
    if (idx >= NROWS * DINNER) return;
    int d   = idx & (DINNER - 1);
    int row = idx >> 10;
    int l   = row & (LSEQ - 1);
    int b   = row >> 11;

    float acc = cb[d];
    float4 w = *(const float4*)(cw + d * 4);
    const float* col = xz + (size_t)(b * LSEQ) * XZCOLS + d;
    if (l >= 3) {
        acc += col[(size_t)(l-3) * XZCOLS] * w.x;
        acc += col[(size_t)(l-2) * XZCOLS] * w.y;
        acc += col[(size_t)(l-1) * XZCOLS] * w.z;
        acc += col[(size_t)(l  ) * XZCOLS] * w.w;
    } else {
        const float wv[4] = {w.x, w.y, w.z, w.w};
        #pragma unroll
        for (int k = 0; k < 4; k++) {
            int ll = l - 3 + k;
            if (ll >= 0) acc += col[(size_t)ll * XZCOLS] * wv[k];
        }
    }
    float sig = 1.f / (1.f + __expf(-acc));
    xc[idx] = acc * sig;
}

// ---------------- dbl = xc @ W_xproj  (N=64, K=1024), 32 rows/block -----
__global__ __launch_bounds__(256) void gemm_dbl_kernel(
    const float* __restrict__ X, const float* __restrict__ W,
    float* __restrict__ O)
{
    __shared__ float Xs[32][33];
    __shared__ float Ws[32][64];
    const int tid = threadIdx.x;
    const int tx = tid & 15, ty = tid >> 4;
    const int row0 = blockIdx.x * 32;
    const int rX = tid >> 3, cX = (tid & 7) * 4;

    float acc[2][4];
    #pragma unroll
    for (int i = 0; i < 2; i++)
        #pragma unroll
        for (int j = 0; j < 4; j++) acc[i][j] = 0.f;

    for (int k0 = 0; k0 < DINNER; k0 += 32) {
        float4 v = *(const float4*)(X + (size_t)(row0 + rX) * DINNER + k0 + cX);
        Xs[cX+0][rX] = v.x; Xs[cX+1][rX] = v.y;
        Xs[cX+2][rX] = v.z; Xs[cX+3][rX] = v.w;
        #pragma unroll
        for (int j = 0; j < 2; j++) {
            int t = tid + j * 256;
            int r = t >> 4, cc = (t & 15) * 4;
            *(float4*)&Ws[r][cc] = *(const float4*)(W + (size_t)(k0 + r) * 64 + cc);
        }
        __syncthreads();
        #pragma unroll
        for (int kk = 0; kk < 32; kk++) {
            float a0 = Xs[kk][ty*2+0];
            float a1 = Xs[kk][ty*2+1];
            float b0 = Ws[kk][tx*4+0], b1 = Ws[kk][tx*4+1];
            float b2 = Ws[kk][tx*4+2], b3 = Ws[kk][tx*4+3];
            acc[0][0] += a0*b0; acc[0][1] += a0*b1; acc[0][2] += a0*b2; acc[0][3] += a0*b3;
            acc[1][0] += a1*b0; acc[1][1] += a1*b1; acc[1][2] += a1*b2; acc[1][3] += a1*b3;
        }
        __syncthreads();
    }
    #pragma unroll
    for (int i = 0; i < 2; i++) {
        float4 v = make_float4(acc[i][0], acc[i][1], acc[i][2], acc[i][3]);
        *(float4*)(O + (size_t)(row0 + ty*2 + i) * 64 + tx*4) = v;
    }
}

// ---------------- dt = softplus(dtr @ W_dt + b_dt)  (K=32) --------------
__global__ __launch_bounds__(256) void dt_kernel(
    const float* __restrict__ dbl, const float* __restrict__ Wdt,
    const float* __restrict__ bdt, float* __restrict__ dt)
{
    __shared__ float dtr[8][32];
    const int tid = threadIdx.x;
    const int row0 = blockIdx.x * 8;
    {
        int r = tid >> 5, c = tid & 31;
        dtr[r][c] = dbl[(size_t)(row0 + r) * DBLCOLS + c];
    }
    __syncthreads();

    const int base = tid * 4;
    float4 bb = *(const float4*)(bdt + base);
    float acc[8][4];
    #pragma unroll
    for (int r = 0; r < 8; r++) {
        acc[r][0] = bb.x; acc[r][1] = bb.y; acc[r][2] = bb.z; acc[r][3] = bb.w;
    }
    #pragma unroll
    for (int k = 0; k < 32; k++) {
        float4 w = *(const float4*)(Wdt + (size_t)k * DINNER + base);
        #pragma unroll
        for (int r = 0; r < 8; r++) {
            float a = dtr[r][k];
            acc[r][0] += a * w.x; acc[r][1] += a * w.y;
            acc[r][2] += a * w.z; acc[r][3] += a * w.w;
        }
    }
    #pragma unroll
    for (int r = 0; r < 8; r++) {
        float o[4];
        #pragma unroll
        for (int j = 0; j < 4; j++) {
            float v = acc[r][j];
            o[j] = (v > 20.f) ? v : log1pf(__expf(v));
        }
        *(float4*)(dt + (size_t)(row0 + r) * DINNER + base) =
            make_float4(o[0], o[1], o[2], o[3]);
    }
}

// ---------------- selective scan: smem-staged + cp.async pipeline -------
#define SCH 8
#define ST  64
#define NCHUNK (LSEQ/ST)

struct ScanBuf {
    float dt[ST][SCH];
    float xc[ST][SCH];
    float zz[ST][SCH];
    float bc[ST][2*DSTATE];
};

__global__ __launch_bounds__(128) void scan_kernel(
    const float* __restrict__ xz, const float* __restrict__ xc,
    const float* __restrict__ dbl, const float* __restrict__ dt,
    const float* __restrict__ A_log, const float* __restrict__ Dp,
    float* __restrict__ y)
{
    __shared__ ScanBuf sb[2];
    __shared__ float sy[ST][SCH];

    const int tid  = threadIdx.x;
    const int lane = tid & 31;
    const int w    = tid >> 5;
    const int half = lane >> 4;
    const int s    = lane & 15;
    const int cl   = w * 2 + half;
    const int chb  = blockIdx.x * SCH;
    const int b    = chb >> 10;
    const int d0   = chb & (DINNER - 1);
    const int d    = d0 + cl;
    const size_t rowb = (size_t)b * LSEQ;

    const float A  = -__expf(A_log[d * DSTATE + s]);
    const float Dd = Dp[d];

    const int tq  = tid >> 1;
    const int qc  = (tid & 1) * 4;

    auto prefetch = [&](int c, int pp) {
        const size_t r0 = rowb + (size_t)c * ST;
        cp16(s2u(&sb[pp].dt[tq][qc]), dt + (r0 + tq) * DINNER + d0 + qc);
        cp16(s2u(&sb[pp].xc[tq][qc]), xc + (r0 + tq) * DINNER + d0 + qc);
        cp16(s2u(&sb[pp].zz[tq][qc]), xz + (r0 + tq) * XZCOLS + DINNER + d0 + qc);
        #pragma unroll
        for (int j = 0; j < 4; j++) {
            int e = tid + j * 128;
            int tt = e >> 3, qq = (e & 7) * 4;
            cp16(s2u(&sb[pp].bc[tt][qq]), dbl + (r0 + tt) * DBLCOLS + DTRANK + qq);
        }
        asm volatile("cp.async.commit_group;\n" ::);
    };

    prefetch(0, 0);
    prefetch(1, 1);

    float h = 0.f;
    for (int c = 0; c < NCHUNK; c++) {
        const int p = c & 1;
        if (c < NCHUNK - 1) asm volatile("cp.async.wait_group 1;\n" ::);
        else                asm volatile("cp.async.wait_group 0;\n" ::);
        __syncthreads();

        #pragma unroll 4
        for (int t = 0; t < ST; t++) {
            float dtv = sb[p].dt[t][cl];
            float xv  = sb[p].xc[t][cl];
            float Bv  = sb[p].bc[t][s];
            float Cv  = sb[p].bc[t][DSTATE + s];
            float e   = __expf(dtv * A);
            h = h * e + dtv * xv * Bv;
            float pr = h * Cv;
            pr += __shfl_xor_sync(0xffffffffu, pr, 8);
            pr += __shfl_xor_sync(0xffffffffu, pr, 4);
            pr += __shfl_xor_sync(0xffffffffu, pr, 2);
            pr += __shfl_xor_sync(0xffffffffu, pr, 1);
            if (s == 0) sy[t][cl] = pr + xv * Dd;
        }
        __syncthreads();

        float4 yv = *(float4*)&sy[tq][qc];
        float4 zv = *(float4*)&sb[p].zz[tq][qc];
        if (c + 2 < NCHUNK) prefetch(c + 2, p);

        float4 o;
        o.x = yv.x * (zv.x / (1.f + __expf(-zv.x)));
        o.y = yv.y * (zv.y / (1.f + __expf(-zv.y)));
        o.z = yv.z * (zv.z / (1.f + __expf(-zv.z)));
        o.w = yv.w * (zv.w / (1.f + __expf(-zv.w)));
        const size_t r0 = rowb + (size_t)c * ST;
        *(float4*)(y + (r0 + tq) * DINNER + d0 + qc) = o;
    }
}

// ---------------- residual + LayerNorm ----------------------------------
__global__ __launch_bounds__(128) void ln_kernel(
    const float* __restrict__ go, const float* __restrict__ x,
    const float* __restrict__ gamma, const float* __restrict__ beta,
    float* __restrict__ out)
{
    const int row = blockIdx.x;
    const int tid = threadIdx.x;
    float4 a  = *(const float4*)(go + (size_t)row * DMODEL + tid * 4);
    float4 xr = *(const float4*)(x  + (size_t)row * DMODEL + tid * 4);
    float v0 = a.x + xr.x, v1 = a.y + xr.y, v2 = a.z + xr.z, v3 = a.w + xr.w;

    float s  = v0 + v1 + v2 + v3;
    float sq = v0*v0 + v1*v1 + v2*v2 + v3*v3;
    #pragma unroll
    for (int o = 16; o > 0; o >>= 1) {
        s  += __shfl_xor_sync(0xffffffffu, s,  o);
        sq += __shfl_xor_sync(0xffffffffu, sq, o);
    }
    __shared__ float ss[4], ssq[4];
    if ((tid & 31) == 0) { ss[tid >> 5] = s; ssq[tid >> 5] = sq; }
    __syncthreads();
    s  = ss[0]  + ss[1]  + ss[2]  + ss[3];
    sq = ssq[0] + ssq[1] + ssq[2] + ssq[3];

    const float mu  = s * (1.f / DMODEL);
    const float var = sq * (1.f / DMODEL) - mu * mu;
    const float inv = rsqrtf(var + 1e-5f);

    float4 g  = *(const float4*)(gamma + tid * 4);
    float4 be = *(const float4*)(beta  + tid * 4);
    float4 o;
    o.x = (v0 - mu) * inv * g.x + be.x;
    o.y = (v1 - mu) * inv * g.y + be.y;
    o.z = (v2 - mu) * inv * g.z + be.z;
    o.w = (v3 - mu) * inv * g.w + be.w;
    *(float4*)(out + (size_t)row * DMODEL + tid * 4) = o;
}

// ---------------- launcher ----------------------------------------------
extern "C" void kernel_launch(void* const* d_in, const int* in_sizes, int n_in,
                              void* d_out, int out_size)
{
    (void)in_sizes; (void)n_in; (void)out_size;
    const float* x      = (const float*)d_in[0];
    const float* W_in   = (const float*)d_in[1];
    const float* conv_w = (const float*)d_in[2];
    const float* conv_b = (const float*)d_in[3];
    const float* W_xprj = (const float*)d_in[4];
    const float* W_dt   = (const float*)d_in[5];
    const float* b_dt   = (const float*)d_in[6];
    const float* A_log  = (const float*)d_in[7];
    const float* Dvec   = (const float*)d_in[8];
    const float* W_out  = (const float*)d_in[9];
    const float* gamma  = (const float*)d_in[10];
    const float* beta   = (const float*)d_in[11];
    float* out = (float*)d_out;

    float *p_xz, *p_xc, *p_dbl, *p_dt, *p_y, *p_o;
    cudaGetSymbolAddress((void**)&p_xz,  g_xz);
    cudaGetSymbolAddress((void**)&p_xc,  g_xc);
    cudaGetSymbolAddress((void**)&p_dbl, g_dbl);
    cudaGetSymbolAddress((void**)&p_dt,  g_dt);
    cudaGetSymbolAddress((void**)&p_y,   g_y);
    cudaGetSymbolAddress((void**)&p_o,   g_o);

    // 1) xz = x @ W_in   (tf32 mma.sync + cp.async pipeline)
    tmma_kernel<<<dim3(XZCOLS/TGN, NROWS/TGM), 256>>>(x, W_in, p_xz, NROWS, XZCOLS, DMODEL);
    // 2) xc = silu(causal_conv(xi) + b)
    conv_silu_kernel<<<(NROWS*DINNER)/256, 256>>>(p_xz, conv_w, conv_b, p_xc);
    // 3) dbl = xc @ W_xproj   (4096x64, K=1024)
    gemm_dbl_kernel<<<NROWS/32, 256>>>(p_xc, W_xprj, p_dbl);
    // 4) dt = softplus(dtr @ W_dt + b_dt)
    dt_kernel<<<NROWS/8, 256>>>(p_dbl, W_dt, b_dt, p_dt);
    // 5) selective scan + D skip + silu(z) gate
    scan_kernel<<<(BATCH*DINNER)/SCH, 128>>>(p_xz, p_xc, p_dbl, p_dt, A_log, Dvec, p_y);
    // 6) o = y @ W_out   (tf32 mma.sync + cp.async pipeline)
    tmma_kernel<<<dim3(DMODEL/TGN, NROWS/TGM), 256>>>(p_y, W_out, p_o, NROWS, DMODEL, DINNER);
    // 7) out = LN(o + x) * gamma + beta
    ln_kernel<<<NROWS, 128>>>(p_o, x, gamma, beta, out);
}

// round 12
// speedup vs baseline: 6.4625x; 1.0629x over previous
#include <cuda_runtime.h>
#include <cuda_bf16.h>
#include <math.h>
#include <stdint.h>

// ---------------- problem constants ----------------
#define BATCH   2
#define LSEQ    2048
#define DMODEL  512
#define DINNER  1024
#define DSTATE  16
#define DTRANK  32
#define NROWS   (BATCH*LSEQ)          // 4096
#define XZCOLS  (2*DINNER)            // 2048
#define DBLCOLS (DTRANK + 2*DSTATE)   // 64

// ---------------- scratch (device globals; no allocation) ----------------
__device__ float g_xz [NROWS * XZCOLS];    // [xi | z]
__device__ float g_xc [NROWS * DINNER];    // conv+silu output
__device__ float g_dbl[NROWS * DBLCOLS];   // [dtr | B | C]
__device__ float g_dt [NROWS * DINNER];    // softplus(dt)
__device__ float g_y  [NROWS * DINNER];    // scan output (gated)
__device__ float g_o  [NROWS * DMODEL];    // pre-LN gemm output

// ---------------- helpers ----------------
__device__ __forceinline__ uint32_t s2u(const void* p) {
    uint32_t a;
    asm("{ .reg .u64 t; cvta.to.shared.u64 t, %1; cvt.u32.u64 %0, t; }"
        : "=r"(a) : "l"(p));
    return a;
}
__device__ __forceinline__ void cp16(uint32_t dst, const void* src) {
    asm volatile("cp.async.cg.shared.global [%0], [%1], 16;\n" :: "r"(dst), "l"(src));
}
// pack two fp32 -> bf16x2 (lo = first arg, hi = second arg)
__device__ __forceinline__ uint32_t pack_bf2(float lo, float hi) {
    uint32_t r;
    asm("cvt.rn.bf16x2.f32 %0, %1, %2;" : "=r"(r) : "f"(hi), "f"(lo));
    return r;
}
__device__ __forceinline__ void mma16(float* c, const uint32_t* a, const uint32_t* b) {
    asm volatile(
        "mma.sync.aligned.m16n8k16.row.col.f32.bf16.bf16.f32 "
        "{%0,%1,%2,%3}, {%4,%5,%6,%7}, {%8,%9}, {%0,%1,%2,%3};"
        : "+f"(c[0]), "+f"(c[1]), "+f"(c[2]), "+f"(c[3])
        : "r"(a[0]), "r"(a[1]), "r"(a[2]), "r"(a[3]), "r"(b[0]), "r"(b[1]));
}

// ---------------- bf16 tensor-core GEMM: C[M,N] = A[M,K] @ B[K,N] -------
// Block tile (MTILES*32) x 128 x 16, 256 thr / 8 warps (2M x 4N).
// A smem [BM][12] u32 = bf16 k-pairs (conflict-free frag loads);
// B smem [8][136] u32 = bf16 k-pairs packed across k (8*tig+gid distinct).
// Register-prefetch double buffer; fp32->bf16 cvt during staging.
// MTILES=4 -> BM=128 ; MTILES=2 -> BM=64 (for small-N GEMM occupancy).
template<int MTILES>
__global__ __launch_bounds__(256) void tmma_kernel(
    const float* __restrict__ A, const float* __restrict__ B,
    float* __restrict__ C, int M, int N, int K)
{
    constexpr int BM = MTILES * 32;
    __shared__ uint32_t As[2][BM][12];
    __shared__ uint32_t Bs[2][8][136];

    const int tid  = threadIdx.x;
    const int wid  = tid >> 5, lane = tid & 31;
    const int gid  = lane >> 2, tig = lane & 3;
    const int wm   = wid & 1,  wn  = wid >> 1;     // 2 x 4 warp grid
    const int m0   = blockIdx.y * BM, n0 = blockIdx.x * 128;

    // ---- staging mappings ----
    // A: BM*16 fp32 -> 256 threads
    int ra, ca;            // row, k-base (float units)
    if (MTILES == 4) { ra = tid >> 1; ca = (tid & 1) * 8; }   // 8 floats/thread
    else             { ra = tid >> 2; ca = (tid & 3) * 4; }   // 4 floats/thread
    // B: 16x128 fp32 -> k-pair packing, 4 u32/thread
    const int kp = tid >> 5;          // 0..7 (k pair index)
    const int nb = (tid & 31) * 4;    // n base

    const float* Aptr = A + (size_t)(m0 + ra) * K + ca;
    const float* B0   = B + (size_t)(2 * kp)     * N + n0 + nb;
    const float* B1   = B + (size_t)(2 * kp + 1) * N + n0 + nb;

    float4 a0, a1, bl, bh;
    auto load_tile = [&](int kt) {
        const int k0 = kt * 16;
        a0 = *(const float4*)(Aptr + k0);
        if (MTILES == 4) a1 = *(const float4*)(Aptr + k0 + 4);
        bl = *(const float4*)(B0 + (size_t)k0 * N);
        bh = *(const float4*)(B1 + (size_t)k0 * N);
    };
    auto stage = [&](int q) {
        if (MTILES == 4) {
            uint4 u = make_uint4(pack_bf2(a0.x, a0.y), pack_bf2(a0.z, a0.w),
                                 pack_bf2(a1.x, a1.y), pack_bf2(a1.z, a1.w));
            *(uint4*)&As[q][ra][(tid & 1) * 4] = u;
        } else {
            uint2 u = make_uint2(pack_bf2(a0.x, a0.y), pack_bf2(a0.z, a0.w));
            *(uint2*)&As[q][ra][(tid & 3) * 2] = u;
        }
        uint4 w = make_uint4(pack_bf2(bl.x, bh.x), pack_bf2(bl.y, bh.y),
                             pack_bf2(bl.z, bh.z), pack_bf2(bl.w, bh.w));
        *(uint4*)&Bs[q][kp][nb] = w;
    };

    float acc[MTILES * 4][4];
    #pragma unroll
    for (int i = 0; i < MTILES * 4; i++)
        #pragma unroll
        for (int j = 0; j < 4; j++) acc[i][j] = 0.f;

    const int ntiles = K >> 4;
    load_tile(0);
    stage(0);
    __syncthreads();

    int p = 0;
    for (int kt = 0; kt < ntiles; kt++) {
        if (kt + 1 < ntiles) load_tile(kt + 1);

        uint32_t af[MTILES][4], bf[4][2];
        #pragma unroll
        for (int i = 0; i < MTILES; i++) {
            const int mr = wm * (MTILES * 16) + i * 16 + gid;
            af[i][0] = As[p][mr    ][tig];
            af[i][1] = As[p][mr + 8][tig];
            af[i][2] = As[p][mr    ][tig + 4];
            af[i][3] = As[p][mr + 8][tig + 4];
        }
        #pragma unroll
        for (int j = 0; j < 4; j++) {
            const int nc = wn * 32 + j * 8 + gid;
            bf[j][0] = Bs[p][tig    ][nc];
            bf[j][1] = Bs[p][tig + 4][nc];
        }
        #pragma unroll
        for (int i = 0; i < MTILES; i++)
            #pragma unroll
            for (int j = 0; j < 4; j++)
                mma16(acc[i * 4 + j], af[i], bf[j]);

        if (kt + 1 < ntiles) stage(p ^ 1);
        __syncthreads();
        p ^= 1;
    }

    // epilogue
    #pragma unroll
    for (int i = 0; i < MTILES; i++) {
        const int row = m0 + wm * (MTILES * 16) + i * 16 + gid;
        #pragma unroll
        for (int j = 0; j < 4; j++) {
            const int col = n0 + wn * 32 + j * 8 + tig * 2;
            float* Cp = C + (size_t)row * N + col;
            *(float2*)Cp = make_float2(acc[i * 4 + j][0], acc[i * 4 + j][1]);
            *(float2*)(Cp + (size_t)8 * N) = make_float2(acc[i * 4 + j][2], acc[i * 4 + j][3]);
        }
    }
}

// ---------------- depthwise causal conv (k=4) + bias + SiLU -------------
__global__ __launch_bounds__(256) void conv_silu_kernel(
    const float* __restrict__ xz, const float* __restrict__ cw,
    const float* __restrict__ cb, float* __restrict__ xc)
{
    int idx = blockIdx.x * 256 + threadIdx.x;
    if (idx >= NROWS * DINNER) return;
    int d   = idx & (DINNER - 1);
    int row = idx >> 10;
    int l   = row & (LSEQ - 1);
    int b   = row >> 11;

    float acc = cb[d];
    float4 w = *(const float4*)(cw + d * 4);
    const float* col = xz + (size_t)(b * LSEQ) * XZCOLS + d;
    if (l >= 3) {
        acc += col[(size_t)(l-3) * XZCOLS] * w.x;
        acc += col[(size_t)(l-2) * XZCOLS] * w.y;
        acc += col[(size_t)(l-1) * XZCOLS] * w.z;
        acc += col[(size_t)(l  ) * XZCOLS] * w.w;
    } else {
        const float wv[4] = {w.x, w.y, w.z, w.w};
        #pragma unroll
        for (int k = 0; k < 4; k++) {
            int ll = l - 3 + k;
            if (ll >= 0) acc += col[(size_t)ll * XZCOLS] * wv[k];
        }
    }
    float sig = 1.f / (1.f + __expf(-acc));
    xc[idx] = acc * sig;
}

// ---------------- dbl = xc @ W_xproj  (N=64, K=1024), 32 rows/block -----
__global__ __launch_bounds__(256) void gemm_dbl_kernel(
    const float* __restrict__ X, const float* __restrict__ W,
    float* __restrict__ O)
{
    __shared__ float Xs[32][33];
    __shared__ float Ws[32][64];
    const int tid = threadIdx.x;
    const int tx = tid & 15, ty = tid >> 4;
    const int row0 = blockIdx.x * 32;
    const int rX = tid >> 3, cX = (tid & 7) * 4;

    float acc[2][4];
    #pragma unroll
    for (int i = 0; i < 2; i++)
        #pragma unroll
        for (int j = 0; j < 4; j++) acc[i][j] = 0.f;

    for (int k0 = 0; k0 < DINNER; k0 += 32) {
        float4 v = *(const float4*)(X + (size_t)(row0 + rX) * DINNER + k0 + cX);
        Xs[cX+0][rX] = v.x; Xs[cX+1][rX] = v.y;
        Xs[cX+2][rX] = v.z; Xs[cX+3][rX] = v.w;
        #pragma unroll
        for (int j = 0; j < 2; j++) {
            int t = tid + j * 256;
            int r = t >> 4, cc = (t & 15) * 4;
            *(float4*)&Ws[r][cc] = *(const float4*)(W + (size_t)(k0 + r) * 64 + cc);
        }
        __syncthreads();
        #pragma unroll
        for (int kk = 0; kk < 32; kk++) {
            float a0 = Xs[kk][ty*2+0];
            float a1 = Xs[kk][ty*2+1];
            float b0 = Ws[kk][tx*4+0], b1 = Ws[kk][tx*4+1];
            float b2 = Ws[kk][tx*4+2], b3 = Ws[kk][tx*4+3];
            acc[0][0] += a0*b0; acc[0][1] += a0*b1; acc[0][2] += a0*b2; acc[0][3] += a0*b3;
            acc[1][0] += a1*b0; acc[1][1] += a1*b1; acc[1][2] += a1*b2; acc[1][3] += a1*b3;
        }
        __syncthreads();
    }
    #pragma unroll
    for (int i = 0; i < 2; i++) {
        float4 v = make_float4(acc[i][0], acc[i][1], acc[i][2], acc[i][3]);
        *(float4*)(O + (size_t)(row0 + ty*2 + i) * 64 + tx*4) = v;
    }
}

// ---------------- dt = softplus(dtr @ W_dt + b_dt)  (K=32) --------------
__global__ __launch_bounds__(256) void dt_kernel(
    const float* __restrict__ dbl, const float* __restrict__ Wdt,
    const float* __restrict__ bdt, float* __restrict__ dt)
{
    __shared__ float dtr[8][32];
    const int tid = threadIdx.x;
    const int row0 = blockIdx.x * 8;
    {
        int r = tid >> 5, c = tid & 31;
        dtr[r][c] = dbl[(size_t)(row0 + r) * DBLCOLS + c];
    }
    __syncthreads();

    const int base = tid * 4;
    float4 bb = *(const float4*)(bdt + base);
    float acc[8][4];
    #pragma unroll
    for (int r = 0; r < 8; r++) {
        acc[r][0] = bb.x; acc[r][1] = bb.y; acc[r][2] = bb.z; acc[r][3] = bb.w;
    }
    #pragma unroll
    for (int k = 0; k < 32; k++) {
        float4 w = *(const float4*)(Wdt + (size_t)k * DINNER + base);
        #pragma unroll
        for (int r = 0; r < 8; r++) {
            float a = dtr[r][k];
            acc[r][0] += a * w.x; acc[r][1] += a * w.y;
            acc[r][2] += a * w.z; acc[r][3] += a * w.w;
        }
    }
    #pragma unroll
    for (int r = 0; r < 8; r++) {
        float o[4];
        #pragma unroll
        for (int j = 0; j < 4; j++) {
            float v = acc[r][j];
            o[j] = (v > 20.f) ? v : log1pf(__expf(v));
        }
        *(float4*)(dt + (size_t)(row0 + r) * DINNER + base) =
            make_float4(o[0], o[1], o[2], o[3]);
    }
}

// ---------------- selective scan: smem-staged + cp.async pipeline -------
#define SCH 8
#define ST  64
#define NCHUNK (LSEQ/ST)

struct ScanBuf {
    float dt[ST][SCH];
    float xc[ST][SCH];
    float zz[ST][SCH];
    float bc[ST][2*DSTATE];
};

__global__ __launch_bounds__(128) void scan_kernel(
    const float* __restrict__ xz, const float* __restrict__ xc,
    const float* __restrict__ dbl, const float* __restrict__ dt,
    const float* __restrict__ A_log, const float* __restrict__ Dp,
    float* __restrict__ y)
{
    __shared__ ScanBuf sb[2];
    __shared__ float sy[ST][SCH];

    const int tid  = threadIdx.x;
    const int lane = tid & 31;
    const int w    = tid >> 5;
    const int half = lane >> 4;
    const int s    = lane & 15;
    const int cl   = w * 2 + half;
    const int chb  = blockIdx.x * SCH;
    const int b    = chb >> 10;
    const int d0   = chb & (DINNER - 1);
    const int d    = d0 + cl;
    const size_t rowb = (size_t)b * LSEQ;

    const float A  = -__expf(A_log[d * DSTATE + s]);
    const float Dd = Dp[d];

    const int tq  = tid >> 1;
    const int qc  = (tid & 1) * 4;

    auto prefetch = [&](int c, int pp) {
        const size_t r0 = rowb + (size_t)c * ST;
        cp16(s2u(&sb[pp].dt[tq][qc]), dt + (r0 + tq) * DINNER + d0 + qc);
        cp16(s2u(&sb[pp].xc[tq][qc]), xc + (r0 + tq) * DINNER + d0 + qc);
        cp16(s2u(&sb[pp].zz[tq][qc]), xz + (r0 + tq) * XZCOLS + DINNER + d0 + qc);
        #pragma unroll
        for (int j = 0; j < 4; j++) {
            int e = tid + j * 128;
            int tt = e >> 3, qq = (e & 7) * 4;
            cp16(s2u(&sb[pp].bc[tt][qq]), dbl + (r0 + tt) * DBLCOLS + DTRANK + qq);
        }
        asm volatile("cp.async.commit_group;\n" ::);
    };

    prefetch(0, 0);
    prefetch(1, 1);

    float h = 0.f;
    for (int c = 0; c < NCHUNK; c++) {
        const int p = c & 1;
        if (c < NCHUNK - 1) asm volatile("cp.async.wait_group 1;\n" ::);
        else                asm volatile("cp.async.wait_group 0;\n" ::);
        __syncthreads();

        #pragma unroll 8
        for (int t = 0; t < ST; t++) {
            float dtv = sb[p].dt[t][cl];
            float xv  = sb[p].xc[t][cl];
            float Bv  = sb[p].bc[t][s];
            float Cv  = sb[p].bc[t][DSTATE + s];
            float e   = __expf(dtv * A);
            h = h * e + dtv * xv * Bv;
            float pr = h * Cv;
            pr += __shfl_xor_sync(0xffffffffu, pr, 8);
            pr += __shfl_xor_sync(0xffffffffu, pr, 4);
            pr += __shfl_xor_sync(0xffffffffu, pr, 2);
            pr += __shfl_xor_sync(0xffffffffu, pr, 1);
            if (s == 0) sy[t][cl] = pr + xv * Dd;
        }
        __syncthreads();

        float4 yv = *(float4*)&sy[tq][qc];
        float4 zv = *(float4*)&sb[p].zz[tq][qc];
        if (c + 2 < NCHUNK) prefetch(c + 2, p);

        float4 o;
        o.x = yv.x * (zv.x / (1.f + __expf(-zv.x)));
        o.y = yv.y * (zv.y / (1.f + __expf(-zv.y)));
        o.z = yv.z * (zv.z / (1.f + __expf(-zv.z)));
        o.w = yv.w * (zv.w / (1.f + __expf(-zv.w)));
        const size_t r0 = rowb + (size_t)c * ST;
        *(float4*)(y + (r0 + tq) * DINNER + d0 + qc) = o;
    }
}

// ---------------- residual + LayerNorm ----------------------------------
__global__ __launch_bounds__(128) void ln_kernel(
    const float* __restrict__ go, const float* __restrict__ x,
    const float* __restrict__ gamma, const float* __restrict__ beta,
    float* __restrict__ out)
{
    const int row = blockIdx.x;
    const int tid = threadIdx.x;
    float4 a  = *(const float4*)(go + (size_t)row * DMODEL + tid * 4);
    float4 xr = *(const float4*)(x  + (size_t)row * DMODEL + tid * 4);
    float v0 = a.x + xr.x, v1 = a.y + xr.y, v2 = a.z + xr.z, v3 = a.w + xr.w;

    float s  = v0 + v1 + v2 + v3;
    float sq = v0*v0 + v1*v1 + v2*v2 + v3*v3;
    #pragma unroll
    for (int o = 16; o > 0; o >>= 1) {
        s  += __shfl_xor_sync(0xffffffffu, s,  o);
        sq += __shfl_xor_sync(0xffffffffu, sq, o);
    }
    __shared__ float ss[4], ssq[4];
    if ((tid & 31) == 0) { ss[tid >> 5] = s; ssq[tid >> 5] = sq; }
    __syncthreads();
    s  = ss[0]  + ss[1]  + ss[2]  + ss[3];
    sq = ssq[0] + ssq[1] + ssq[2] + ssq[3];

    const float mu  = s * (1.f / DMODEL);
    const float var = sq * (1.f / DMODEL) - mu * mu;
    const float inv = rsqrtf(var + 1e-5f);

    float4 g  = *(const float4*)(gamma + tid * 4);
    float4 be = *(const float4*)(beta  + tid * 4);
    float4 o;
    o.x = (v0 - mu) * inv * g.x + be.x;
    o.y = (v1 - mu) * inv * g.y + be.y;
    o.z = (v2 - mu) * inv * g.z + be.z;
    o.w = (v3 - mu) * inv * g.w + be.w;
    *(float4*)(out + (size_t)row * DMODEL + tid * 4) = o;
}

// ---------------- launcher ----------------------------------------------
extern "C" void kernel_launch(void* const* d_in, const int* in_sizes, int n_in,
                              void* d_out, int out_size)
{
    (void)in_sizes; (void)n_in; (void)out_size;
    const float* x      = (const float*)d_in[0];
    const float* W_in   = (const float*)d_in[1];
    const float* conv_w = (const float*)d_in[2];
    const float* conv_b = (const float*)d_in[3];
    const float* W_xprj = (const float*)d_in[4];
    const float* W_dt   = (const float*)d_in[5];
    const float* b_dt   = (const float*)d_in[6];
    const float* A_log  = (const float*)d_in[7];
    const float* Dvec   = (const float*)d_in[8];
    const float* W_out  = (const float*)d_in[9];
    const float* gamma  = (const float*)d_in[10];
    const float* beta   = (const float*)d_in[11];
    float* out = (float*)d_out;

    float *p_xz, *p_xc, *p_dbl, *p_dt, *p_y, *p_o;
    cudaGetSymbolAddress((void**)&p_xz,  g_xz);
    cudaGetSymbolAddress((void**)&p_xc,  g_xc);
    cudaGetSymbolAddress((void**)&p_dbl, g_dbl);
    cudaGetSymbolAddress((void**)&p_dt,  g_dt);
    cudaGetSymbolAddress((void**)&p_y,   g_y);
    cudaGetSymbolAddress((void**)&p_o,   g_o);

    // 1) xz = x @ W_in   (bf16 mma.sync m16n8k16, BM=128)
    tmma_kernel<4><<<dim3(XZCOLS/128, NROWS/128), 256>>>(x, W_in, p_xz, NROWS, XZCOLS, DMODEL);
    // 2) xc = silu(causal_conv(xi) + b)
    conv_silu_kernel<<<(NROWS*DINNER)/256, 256>>>(p_xz, conv_w, conv_b, p_xc);
    // 3) dbl = xc @ W_xproj   (4096x64, K=1024)
    gemm_dbl_kernel<<<NROWS/32, 256>>>(p_xc, W_xprj, p_dbl);
    // 4) dt = softplus(dtr @ W_dt + b_dt)
    dt_kernel<<<NROWS/8, 256>>>(p_dbl, W_dt, b_dt, p_dt);
    // 5) selective scan + D skip + silu(z) gate
    scan_kernel<<<(BATCH*DINNER)/SCH, 128>>>(p_xz, p_xc, p_dbl, p_dt, A_log, Dvec, p_y);
    // 6) o = y @ W_out   (bf16 mma.sync m16n8k16, BM=64 -> 256 CTAs)
    tmma_kernel<2><<<dim3(DMODEL/128, NROWS/64), 256>>>(p_y, W_out, p_o, NROWS, DMODEL, DINNER);
    // 7) out = LN(o + x) * gamma + beta
    ln_kernel<<<NROWS, 128>>>(p_o, x, gamma, beta, out);
}

// round 13
// speedup vs baseline: 7.1467x; 1.1059x over previous
#include <cuda_runtime.h>
#include <cuda_bf16.h>
#include <math.h>
#include <stdint.h>

// ---------------- problem constants ----------------
#define BATCH   2
#define LSEQ    2048
#define DMODEL  512
#define DINNER  1024
#define DSTATE  16
#define DTRANK  32
#define NROWS   (BATCH*LSEQ)          // 4096
#define XZCOLS  (2*DINNER)            // 2048
#define DBLCOLS (DTRANK + 2*DSTATE)   // 64

// ---------------- scratch (device globals; no allocation) ----------------
__device__ float    g_xz [NROWS * XZCOLS];      // [xi | z]
__device__ float    g_xc [NROWS * DINNER];      // conv+silu output
__device__ float    g_dbl[NROWS * DBLCOLS];     // [dtr | B | C]
__device__ float    g_dt [NROWS * DINNER];      // softplus(dt)
__device__ float    g_o  [NROWS * DMODEL];      // pre-LN gemm output
__device__ uint32_t g_xb  [NROWS * DMODEL / 2];   // x as bf16 pairs (row-major)
__device__ uint32_t g_ybf [NROWS * DINNER / 2];   // y as bf16 pairs (row-major)
__device__ uint32_t g_wpin [(DMODEL/2) * XZCOLS]; // W_in  k-pair packed [K/2][N]
__device__ uint32_t g_wpout[(DINNER/2) * DMODEL]; // W_out k-pair packed [K/2][N]

// ---------------- helpers ----------------
__device__ __forceinline__ uint32_t s2u(const void* p) {
    uint32_t a;
    asm("{ .reg .u64 t; cvta.to.shared.u64 t, %1; cvt.u32.u64 %0, t; }"
        : "=r"(a) : "l"(p));
    return a;
}
__device__ __forceinline__ void cp16(uint32_t dst, const void* src) {
    asm volatile("cp.async.cg.shared.global [%0], [%1], 16;\n" :: "r"(dst), "l"(src));
}
// pack two fp32 -> bf16x2 (lo = first arg in low half)
__device__ __forceinline__ uint32_t pack_bf2(float lo, float hi) {
    uint32_t r;
    asm("cvt.rn.bf16x2.f32 %0, %1, %2;" : "=r"(r) : "f"(hi), "f"(lo));
    return r;
}
__device__ __forceinline__ void mma16(float* c, const uint32_t* a, const uint32_t* b) {
    asm volatile(
        "mma.sync.aligned.m16n8k16.row.col.f32.bf16.bf16.f32 "
        "{%0,%1,%2,%3}, {%4,%5,%6,%7}, {%8,%9}, {%0,%1,%2,%3};"
        : "+f"(c[0]), "+f"(c[1]), "+f"(c[2]), "+f"(c[3])
        : "r"(a[0]), "r"(a[1]), "r"(a[2]), "r"(a[3]), "r"(b[0]), "r"(b[1]));
}

// ---------------- cvt/pack: x -> bf16 pairs, W -> k-pair packed ---------
__global__ __launch_bounds__(256) void cvt_pack_kernel(
    const float* __restrict__ x, const float* __restrict__ Win,
    const float* __restrict__ Wout, uint32_t* __restrict__ xb,
    uint32_t* __restrict__ wpin, uint32_t* __restrict__ wpout)
{
    const int NX  = NROWS * DMODEL / 2;
    const int NWI = (DMODEL/2) * XZCOLS;
    const int NWO = (DINNER/2) * DMODEL;
    int i = blockIdx.x * 256 + threadIdx.x;
    if (i < NX) {
        xb[i] = pack_bf2(x[2*i], x[2*i + 1]);
    } else if (i < NX + NWI) {
        int j = i - NX;
        int kp = j / XZCOLS, n = j - kp * XZCOLS;
        wpin[j] = pack_bf2(Win[(size_t)(2*kp) * XZCOLS + n],
                           Win[(size_t)(2*kp+1) * XZCOLS + n]);
    } else if (i < NX + NWI + NWO) {
        int j = i - NX - NWI;
        int kp = j / DMODEL, n = j - kp * DMODEL;
        wpout[j] = pack_bf2(Wout[(size_t)(2*kp) * DMODEL + n],
                            Wout[(size_t)(2*kp+1) * DMODEL + n]);
    }
}

// ---------------- bf16 tensor-core GEMM (pre-packed operands) -----------
// C[M,N] = A[M,K] @ B[K,N]. A: bf16 row-major as u32 k-pairs [M][K/2].
// B: k-pair packed u32 [K/2][N]. 3-stage cp.async pipeline, pure copies.
// Block tile (MTILES*32) x 128 x 16, 256 thr / 8 warps (2M x 4N).
template<int MTILES>
__global__ __launch_bounds__(256) void tmma_kernel(
    const uint32_t* __restrict__ A, const uint32_t* __restrict__ B,
    float* __restrict__ C, int M, int N, int K)
{
    constexpr int BM  = MTILES * 32;
    constexpr int NST = 3;
    __shared__ uint32_t As[NST][BM][12];   // cols 0..7 data, pad->12 (conflict-free)
    __shared__ uint32_t Bs[NST][8][136];

    const int tid  = threadIdx.x;
    const int wid  = tid >> 5, lane = tid & 31;
    const int gid  = lane >> 2, tig = lane & 3;
    const int wm   = wid & 1,  wn  = wid >> 1;     // 2 x 4 warp grid
    const int m0   = blockIdx.y * BM, n0 = blockIdx.x * 128;
    const int Ku   = K >> 1;                       // u32 per A row

    // A staging: BM rows x 2 halves (16B each)
    const int arow = tid >> 1, ahalf = (tid & 1) * 4;
    // B staging: 8 k-pair rows x 32 quads
    const int kp = tid >> 5, nq = (tid & 31) * 4;

    const uint32_t* Aptr = A + (size_t)(m0 + arow) * Ku + ahalf;
    const uint32_t* Bptr = B + (size_t)kp * N + n0 + nq;

    auto stage = [&](int s, int kt) {
        if (MTILES == 4 || tid < 128)
            cp16(s2u(&As[s][arow][ahalf]), Aptr + kt * 8);
        cp16(s2u(&Bs[s][kp][nq]), Bptr + (size_t)(kt * 8) * N);
        asm volatile("cp.async.commit_group;\n" ::);
    };

    float acc[MTILES * 4][4];
    #pragma unroll
    for (int i = 0; i < MTILES * 4; i++)
        #pragma unroll
        for (int j = 0; j < 4; j++) acc[i][j] = 0.f;

    const int ntiles = K >> 4;
    stage(0, 0);
    stage(1, 1);

    for (int kt = 0; kt < ntiles; kt++) {
        const int p = kt % NST;
        if (kt < ntiles - 1) asm volatile("cp.async.wait_group 1;\n" ::);
        else                 asm volatile("cp.async.wait_group 0;\n" ::);
        __syncthreads();
        if (kt + 2 < ntiles) stage((kt + 2) % NST, kt + 2);

        uint32_t af[MTILES][4], bf[4][2];
        #pragma unroll
        for (int i = 0; i < MTILES; i++) {
            const int mr = wm * (MTILES * 16) + i * 16 + gid;
            af[i][0] = As[p][mr    ][tig];
            af[i][1] = As[p][mr + 8][tig];
            af[i][2] = As[p][mr    ][tig + 4];
            af[i][3] = As[p][mr + 8][tig + 4];
        }
        #pragma unroll
        for (int j = 0; j < 4; j++) {
            const int nc = wn * 32 + j * 8 + gid;
            bf[j][0] = Bs[p][tig    ][nc];
            bf[j][1] = Bs[p][tig + 4][nc];
        }
        #pragma unroll
        for (int i = 0; i < MTILES; i++)
            #pragma unroll
            for (int j = 0; j < 4; j++)
                mma16(acc[i * 4 + j], af[i], bf[j]);
        __syncthreads();
    }

    #pragma unroll
    for (int i = 0; i < MTILES; i++) {
        const int row = m0 + wm * (MTILES * 16) + i * 16 + gid;
        #pragma unroll
        for (int j = 0; j < 4; j++) {
            const int col = n0 + wn * 32 + j * 8 + tig * 2;
            float* Cp = C + (size_t)row * N + col;
            *(float2*)Cp = make_float2(acc[i * 4 + j][0], acc[i * 4 + j][1]);
            *(float2*)(Cp + (size_t)8 * N) = make_float2(acc[i * 4 + j][2], acc[i * 4 + j][3]);
        }
    }
}

// ---------------- depthwise causal conv (k=4) + bias + SiLU -------------
__global__ __launch_bounds__(256) void conv_silu_kernel(
    const float* __restrict__ xz, const float* __restrict__ cw,
    const float* __restrict__ cb, float* __restrict__ xc)
{
    int idx = blockIdx.x * 256 + threadIdx.x;
    if (idx >= NROWS * DINNER) return;
    int d   = idx & (DINNER - 1);
    int row = idx >> 10;
    int l   = row & (LSEQ - 1);
    int b   = row >> 11;

    float acc = cb[d];
    float4 w = *(const float4*)(cw + d * 4);
    const float* col = xz + (size_t)(b * LSEQ) * XZCOLS + d;
    if (l >= 3) {
        acc += col[(size_t)(l-3) * XZCOLS] * w.x;
        acc += col[(size_t)(l-2) * XZCOLS] * w.y;
        acc += col[(size_t)(l-1) * XZCOLS] * w.z;
        acc += col[(size_t)(l  ) * XZCOLS] * w.w;
    } else {
        const float wv[4] = {w.x, w.y, w.z, w.w};
        #pragma unroll
        for (int k = 0; k < 4; k++) {
            int ll = l - 3 + k;
            if (ll >= 0) acc += col[(size_t)ll * XZCOLS] * wv[k];
        }
    }
    float sig = 1.f / (1.f + __expf(-acc));
    xc[idx] = acc * sig;
}

// ---------------- dbl = xc @ W_xproj  (N=64, K=1024), 32 rows/block -----
__global__ __launch_bounds__(256) void gemm_dbl_kernel(
    const float* __restrict__ X, const float* __restrict__ W,
    float* __restrict__ O)
{
    __shared__ float Xs[32][33];
    __shared__ float Ws[32][64];
    const int tid = threadIdx.x;
    const int tx = tid & 15, ty = tid >> 4;
    const int row0 = blockIdx.x * 32;
    const int rX = tid >> 3, cX = (tid & 7) * 4;

    float acc[2][4];
    #pragma unroll
    for (int i = 0; i < 2; i++)
        #pragma unroll
        for (int j = 0; j < 4; j++) acc[i][j] = 0.f;

    for (int k0 = 0; k0 < DINNER; k0 += 32) {
        float4 v = *(const float4*)(X + (size_t)(row0 + rX) * DINNER + k0 + cX);
        Xs[cX+0][rX] = v.x; Xs[cX+1][rX] = v.y;
        Xs[cX+2][rX] = v.z; Xs[cX+3][rX] = v.w;
        #pragma unroll
        for (int j = 0; j < 2; j++) {
            int t = tid + j * 256;
            int r = t >> 4, cc = (t & 15) * 4;
            *(float4*)&Ws[r][cc] = *(const float4*)(W + (size_t)(k0 + r) * 64 + cc);
        }
        __syncthreads();
        #pragma unroll
        for (int kk = 0; kk < 32; kk++) {
            float a0 = Xs[kk][ty*2+0];
            float a1 = Xs[kk][ty*2+1];
            float b0 = Ws[kk][tx*4+0], b1 = Ws[kk][tx*4+1];
            float b2 = Ws[kk][tx*4+2], b3 = Ws[kk][tx*4+3];
            acc[0][0] += a0*b0; acc[0][1] += a0*b1; acc[0][2] += a0*b2; acc[0][3] += a0*b3;
            acc[1][0] += a1*b0; acc[1][1] += a1*b1; acc[1][2] += a1*b2; acc[1][3] += a1*b3;
        }
        __syncthreads();
    }
    #pragma unroll
    for (int i = 0; i < 2; i++) {
        float4 v = make_float4(acc[i][0], acc[i][1], acc[i][2], acc[i][3]);
        *(float4*)(O + (size_t)(row0 + ty*2 + i) * 64 + tx*4) = v;
    }
}

// ---------------- dt = softplus(dtr @ W_dt + b_dt)  (K=32) --------------
__global__ __launch_bounds__(256) void dt_kernel(
    const float* __restrict__ dbl, const float* __restrict__ Wdt,
    const float* __restrict__ bdt, float* __restrict__ dt)
{
    __shared__ float dtr[8][32];
    const int tid = threadIdx.x;
    const int row0 = blockIdx.x * 8;
    {
        int r = tid >> 5, c = tid & 31;
        dtr[r][c] = dbl[(size_t)(row0 + r) * DBLCOLS + c];
    }
    __syncthreads();

    const int base = tid * 4;
    float4 bb = *(const float4*)(bdt + base);
    float acc[8][4];
    #pragma unroll
    for (int r = 0; r < 8; r++) {
        acc[r][0] = bb.x; acc[r][1] = bb.y; acc[r][2] = bb.z; acc[r][3] = bb.w;
    }
    #pragma unroll
    for (int k = 0; k < 32; k++) {
        float4 w = *(const float4*)(Wdt + (size_t)k * DINNER + base);
        #pragma unroll
        for (int r = 0; r < 8; r++) {
            float a = dtr[r][k];
            acc[r][0] += a * w.x; acc[r][1] += a * w.y;
            acc[r][2] += a * w.z; acc[r][3] += a * w.w;
        }
    }
    #pragma unroll
    for (int r = 0; r < 8; r++) {
        float o[4];
        #pragma unroll
        for (int j = 0; j < 4; j++) {
            float v = acc[r][j];
            o[j] = (v > 20.f) ? v : log1pf(__expf(v));
        }
        *(float4*)(dt + (size_t)(row0 + r) * DINNER + base) =
            make_float4(o[0], o[1], o[2], o[3]);
    }
}

// ---------------- selective scan v3: 8 lanes/channel, 2 states/lane -----
// Block: 64 thr = 2 warps = 8 channels (warp = 4 ch x 8 lanes).
// Chunks of 64 timesteps double-buffered via cp.async. Emits y as bf16.
#define SCH 8
#define ST  64
#define NCHUNK (LSEQ/ST)

struct ScanBuf {
    float dt[ST][SCH];
    float xc[ST][SCH];
    float zz[ST][SCH];
    float bc[ST][2*DSTATE];
};

__global__ __launch_bounds__(64) void scan_kernel(
    const float* __restrict__ xz, const float* __restrict__ xc,
    const float* __restrict__ dbl, const float* __restrict__ dt,
    const float* __restrict__ A_log, const float* __restrict__ Dp,
    uint32_t* __restrict__ ybf)
{
    __shared__ ScanBuf sb[2];
    __shared__ float sy[ST][SCH];

    const int tid  = threadIdx.x;          // 0..63
    const int lane = tid & 31;
    const int w    = tid >> 5;
    const int sg   = lane & 7;             // state group: states 2sg, 2sg+1
    const int cl   = w * 4 + (lane >> 3);  // local channel 0..7
    const int chb  = blockIdx.x * SCH;
    const int b    = chb >> 10;
    const int d0   = chb & (DINNER - 1);
    const int d    = d0 + cl;
    const size_t rowb = (size_t)b * LSEQ;

    const float A0 = -__expf(A_log[d * DSTATE + 2*sg    ]);
    const float A1 = -__expf(A_log[d * DSTATE + 2*sg + 1]);
    const float Dd = Dp[d];

    auto prefetch = [&](int c, int pp) {
        const size_t r0 = rowb + (size_t)c * ST;
        #pragma unroll
        for (int j = 0; j < 2; j++) {
            int u = tid + j * 64;
            int rw = u >> 1, qq = (u & 1) * 4;
            cp16(s2u(&sb[pp].dt[rw][qq]), dt + (r0 + rw) * DINNER + d0 + qq);
            cp16(s2u(&sb[pp].xc[rw][qq]), xc + (r0 + rw) * DINNER + d0 + qq);
            cp16(s2u(&sb[pp].zz[rw][qq]), xz + (r0 + rw) * XZCOLS + DINNER + d0 + qq);
        }
        #pragma unroll
        for (int j = 0; j < 8; j++) {
            int u = tid + j * 64;
            int rw = u >> 3, qq = (u & 7) * 4;
            cp16(s2u(&sb[pp].bc[rw][qq]), dbl + (r0 + rw) * DBLCOLS + DTRANK + qq);
        }
        asm volatile("cp.async.commit_group;\n" ::);
    };

    prefetch(0, 0);
    prefetch(1, 1);

    float h0 = 0.f, h1 = 0.f;
    for (int c = 0; c < NCHUNK; c++) {
        const int p = c & 1;
        if (c < NCHUNK - 1) asm volatile("cp.async.wait_group 1;\n" ::);
        else                asm volatile("cp.async.wait_group 0;\n" ::);
        __syncthreads();

        #pragma unroll 8
        for (int t = 0; t < ST; t++) {
            float dtv = sb[p].dt[t][cl];
            float xv  = sb[p].xc[t][cl];
            float2 Bv = *(const float2*)&sb[p].bc[t][2*sg];
            float2 Cv = *(const float2*)&sb[p].bc[t][DSTATE + 2*sg];
            float e0 = __expf(dtv * A0);
            float e1 = __expf(dtv * A1);
            float dx = dtv * xv;
            h0 = h0 * e0 + dx * Bv.x;
            h1 = h1 * e1 + dx * Bv.y;
            float pr = h0 * Cv.x + h1 * Cv.y;
            pr += __shfl_xor_sync(0xffffffffu, pr, 4);
            pr += __shfl_xor_sync(0xffffffffu, pr, 2);
            pr += __shfl_xor_sync(0xffffffffu, pr, 1);
            if (sg == 0) sy[t][cl] = pr + xv * Dd;
        }
        __syncthreads();

        // flush: read sy + z into regs, sync, re-arm buffer, then store bf16 y
        float2 yv[4], zv[4];
        #pragma unroll
        for (int j = 0; j < 4; j++) {
            int u = tid + j * 64;
            int rw = u >> 2, p2 = (u & 3) * 2;
            yv[j] = *(const float2*)&sy[rw][p2];
            zv[j] = *(const float2*)&sb[p].zz[rw][p2];
        }
        __syncthreads();
        if (c + 2 < NCHUNK) prefetch(c + 2, p);

        const size_t r0 = rowb + (size_t)c * ST;
        #pragma unroll
        for (int j = 0; j < 4; j++) {
            int u = tid + j * 64;
            int rw = u >> 2, pi = (u & 3);
            float s0 = zv[j].x / (1.f + __expf(-zv[j].x));
            float s1 = zv[j].y / (1.f + __expf(-zv[j].y));
            ybf[(r0 + rw) * (DINNER/2) + (d0 >> 1) + pi] =
                pack_bf2(yv[j].x * s0, yv[j].y * s1);
        }
    }
}

// ---------------- residual + LayerNorm ----------------------------------
__global__ __launch_bounds__(128) void ln_kernel(
    const float* __restrict__ go, const float* __restrict__ x,
    const float* __restrict__ gamma, const float* __restrict__ beta,
    float* __restrict__ out)
{
    const int row = blockIdx.x;
    const int tid = threadIdx.x;
    float4 a  = *(const float4*)(go + (size_t)row * DMODEL + tid * 4);
    float4 xr = *(const float4*)(x  + (size_t)row * DMODEL + tid * 4);
    float v0 = a.x + xr.x, v1 = a.y + xr.y, v2 = a.z + xr.z, v3 = a.w + xr.w;

    float s  = v0 + v1 + v2 + v3;
    float sq = v0*v0 + v1*v1 + v2*v2 + v3*v3;
    #pragma unroll
    for (int o = 16; o > 0; o >>= 1) {
        s  += __shfl_xor_sync(0xffffffffu, s,  o);
        sq += __shfl_xor_sync(0xffffffffu, sq, o);
    }
    __shared__ float ss[4], ssq[4];
    if ((tid & 31) == 0) { ss[tid >> 5] = s; ssq[tid >> 5] = sq; }
    __syncthreads();
    s  = ss[0]  + ss[1]  + ss[2]  + ss[3];
    sq = ssq[0] + ssq[1] + ssq[2] + ssq[3];

    const float mu  = s * (1.f / DMODEL);
    const float var = sq * (1.f / DMODEL) - mu * mu;
    const float inv = rsqrtf(var + 1e-5f);

    float4 g  = *(const float4*)(gamma + tid * 4);
    float4 be = *(const float4*)(beta  + tid * 4);
    float4 o;
    o.x = (v0 - mu) * inv * g.x + be.x;
    o.y = (v1 - mu) * inv * g.y + be.y;
    o.z = (v2 - mu) * inv * g.z + be.z;
    o.w = (v3 - mu) * inv * g.w + be.w;
    *(float4*)(out + (size_t)row * DMODEL + tid * 4) = o;
}

// ---------------- launcher ----------------------------------------------
extern "C" void kernel_launch(void* const* d_in, const int* in_sizes, int n_in,
                              void* d_out, int out_size)
{
    (void)in_sizes; (void)n_in; (void)out_size;
    const float* x      = (const float*)d_in[0];
    const float* W_in   = (const float*)d_in[1];
    const float* conv_w = (const float*)d_in[2];
    const float* conv_b = (const float*)d_in[3];
    const float* W_xprj = (const float*)d_in[4];
    const float* W_dt   = (const float*)d_in[5];
    const float* b_dt   = (const float*)d_in[6];
    const float* A_log  = (const float*)d_in[7];
    const float* Dvec   = (const float*)d_in[8];
    const float* W_out  = (const float*)d_in[9];
    const float* gamma  = (const float*)d_in[10];
    const float* beta   = (const float*)d_in[11];
    float* out = (float*)d_out;

    float *p_xz, *p_xc, *p_dbl, *p_dt, *p_o;
    uint32_t *p_xb, *p_ybf, *p_wpin, *p_wpout;
    cudaGetSymbolAddress((void**)&p_xz,    g_xz);
    cudaGetSymbolAddress((void**)&p_xc,    g_xc);
    cudaGetSymbolAddress((void**)&p_dbl,   g_dbl);
    cudaGetSymbolAddress((void**)&p_dt,    g_dt);
    cudaGetSymbolAddress((void**)&p_o,     g_o);
    cudaGetSymbolAddress((void**)&p_xb,    g_xb);
    cudaGetSymbolAddress((void**)&p_ybf,   g_ybf);
    cudaGetSymbolAddress((void**)&p_wpin,  g_wpin);
    cudaGetSymbolAddress((void**)&p_wpout, g_wpout);

    const int NCVT = NROWS*DMODEL/2 + (DMODEL/2)*XZCOLS + (DINNER/2)*DMODEL;

    // 0) pack x / W_in / W_out to bf16 operand layouts
    cvt_pack_kernel<<<(NCVT + 255) / 256, 256>>>(x, W_in, W_out, p_xb, p_wpin, p_wpout);
    // 1) xz = x @ W_in   (bf16 mma, pure cp.async operands)
    tmma_kernel<4><<<dim3(XZCOLS/128, NROWS/128), 256>>>(p_xb, p_wpin, p_xz, NROWS, XZCOLS, DMODEL);
    // 2) xc = silu(causal_conv(xi) + b)
    conv_silu_kernel<<<(NROWS*DINNER)/256, 256>>>(p_xz, conv_w, conv_b, p_xc);
    // 3) dbl = xc @ W_xproj
    gemm_dbl_kernel<<<NROWS/32, 256>>>(p_xc, W_xprj, p_dbl);
    // 4) dt = softplus(dtr @ W_dt + b_dt)
    dt_kernel<<<NROWS/8, 256>>>(p_dbl, W_dt, b_dt, p_dt);
    // 5) selective scan (8 lanes/channel) -> y in bf16
    scan_kernel<<<(BATCH*DINNER)/SCH, 64>>>(p_xz, p_xc, p_dbl, p_dt, A_log, Dvec, p_ybf);
    // 6) o = y @ W_out   (bf16 mma, BM=64)
    tmma_kernel<2><<<dim3(DMODEL/128, NROWS/64), 256>>>(p_ybf, p_wpout, p_o, NROWS, DMODEL, DINNER);
    // 7) out = LN(o + x) * gamma + beta
    ln_kernel<<<NROWS, 128>>>(p_o, x, gamma, beta, out);
}

// round 14
// speedup vs baseline: 7.5434x; 1.0555x over previous
#include <cuda_runtime.h>
#include <cuda_bf16.h>
#include <math.h>
#include <stdint.h>

// ---------------- problem constants ----------------
#define BATCH   2
#define LSEQ    2048
#define DMODEL  512
#define DINNER  1024
#define DSTATE  16
#define DTRANK  32
#define NROWS   (BATCH*LSEQ)          // 4096
#define XZCOLS  (2*DINNER)            // 2048
#define DBLCOLS (DTRANK + 2*DSTATE)   // 64

// ---------------- scratch (device globals; no allocation) ----------------
__device__ float    g_xz [NROWS * XZCOLS];      // [xi | z]
__device__ float    g_xc [NROWS * DINNER];      // conv+silu output
__device__ float    g_dbl[NROWS * DBLCOLS];     // [dtr | B | C]
__device__ float    g_dt [NROWS * DINNER];      // softplus(dt)
__device__ float    g_o  [NROWS * DMODEL];      // pre-LN gemm output
__device__ uint32_t g_xb  [NROWS * DMODEL / 2];   // x as bf16 pairs (row-major)
__device__ uint32_t g_ybf [NROWS * DINNER / 2];   // y as bf16 pairs (row-major)
__device__ uint32_t g_wpin [(DMODEL/2) * XZCOLS]; // W_in  k-pair packed [K/2][N]
__device__ uint32_t g_wpout[(DINNER/2) * DMODEL]; // W_out k-pair packed [K/2][N]

// ---------------- helpers ----------------
__device__ __forceinline__ uint32_t s2u(const void* p) {
    uint32_t a;
    asm("{ .reg .u64 t; cvta.to.shared.u64 t, %1; cvt.u32.u64 %0, t; }"
        : "=r"(a) : "l"(p));
    return a;
}
__device__ __forceinline__ void cp16(uint32_t dst, const void* src) {
    asm volatile("cp.async.cg.shared.global [%0], [%1], 16;\n" :: "r"(dst), "l"(src));
}
// pack two fp32 -> bf16x2 (lo = first arg in low half)
__device__ __forceinline__ uint32_t pack_bf2(float lo, float hi) {
    uint32_t r;
    asm("cvt.rn.bf16x2.f32 %0, %1, %2;" : "=r"(r) : "f"(hi), "f"(lo));
    return r;
}
__device__ __forceinline__ void mma16(float* c, const uint32_t* a, const uint32_t* b) {
    asm volatile(
        "mma.sync.aligned.m16n8k16.row.col.f32.bf16.bf16.f32 "
        "{%0,%1,%2,%3}, {%4,%5,%6,%7}, {%8,%9}, {%0,%1,%2,%3};"
        : "+f"(c[0]), "+f"(c[1]), "+f"(c[2]), "+f"(c[3])
        : "r"(a[0]), "r"(a[1]), "r"(a[2]), "r"(a[3]), "r"(b[0]), "r"(b[1]));
}

// ---------------- cvt/pack: x/W -> bf16 layouts, zero dbl ---------------
__global__ __launch_bounds__(256) void cvt_pack_kernel(
    const float* __restrict__ x, const float* __restrict__ Win,
    const float* __restrict__ Wout, uint32_t* __restrict__ xb,
    uint32_t* __restrict__ wpin, uint32_t* __restrict__ wpout,
    float4* __restrict__ dblz)
{
    const int NX  = NROWS * DMODEL / 2;
    const int NWI = (DMODEL/2) * XZCOLS;
    const int NWO = (DINNER/2) * DMODEL;
    const int NZ  = NROWS * DBLCOLS / 4;
    int i = blockIdx.x * 256 + threadIdx.x;
    if (i < NX) {
        xb[i] = pack_bf2(x[2*i], x[2*i + 1]);
    } else if (i < NX + NWI) {
        int j = i - NX;
        int kp = j / XZCOLS, n = j - kp * XZCOLS;
        wpin[j] = pack_bf2(Win[(size_t)(2*kp) * XZCOLS + n],
                           Win[(size_t)(2*kp+1) * XZCOLS + n]);
    } else if (i < NX + NWI + NWO) {
        int j = i - NX - NWI;
        int kp = j / DMODEL, n = j - kp * DMODEL;
        wpout[j] = pack_bf2(Wout[(size_t)(2*kp) * DMODEL + n],
                            Wout[(size_t)(2*kp+1) * DMODEL + n]);
    } else if (i < NX + NWI + NWO + NZ) {
        dblz[i - NX - NWI - NWO] = make_float4(0.f, 0.f, 0.f, 0.f);
    }
}

// ---------------- bf16 tensor-core GEMM (pre-packed operands) -----------
// C[M,N] = A[M,K] @ B[K,N]. A: bf16 row-major as u32 k-pairs [M][K/2].
// B: k-pair packed u32 [K/2][N]. 3-stage cp.async pipeline, pure copies.
// Block tile (MTILES*32) x 128 x 16, 256 thr / 8 warps (2M x 4N).
template<int MTILES>
__global__ __launch_bounds__(256) void tmma_kernel(
    const uint32_t* __restrict__ A, const uint32_t* __restrict__ B,
    float* __restrict__ C, int M, int N, int K)
{
    constexpr int BM  = MTILES * 32;
    constexpr int NST = 3;
    __shared__ uint32_t As[NST][BM][12];   // cols 0..7 data, pad->12 (conflict-free)
    __shared__ uint32_t Bs[NST][8][136];

    const int tid  = threadIdx.x;
    const int wid  = tid >> 5, lane = tid & 31;
    const int gid  = lane >> 2, tig = lane & 3;
    const int wm   = wid & 1,  wn  = wid >> 1;     // 2 x 4 warp grid
    const int m0   = blockIdx.y * BM, n0 = blockIdx.x * 128;
    const int Ku   = K >> 1;                       // u32 per A row

    const int arow = tid >> 1, ahalf = (tid & 1) * 4;
    const int kp = tid >> 5, nq = (tid & 31) * 4;

    const uint32_t* Aptr = A + (size_t)(m0 + arow) * Ku + ahalf;
    const uint32_t* Bptr = B + (size_t)kp * N + n0 + nq;

    auto stage = [&](int s, int kt) {
        if (MTILES == 4 || tid < 128)
            cp16(s2u(&As[s][arow][ahalf]), Aptr + kt * 8);
        cp16(s2u(&Bs[s][kp][nq]), Bptr + (size_t)(kt * 8) * N);
        asm volatile("cp.async.commit_group;\n" ::);
    };

    float acc[MTILES * 4][4];
    #pragma unroll
    for (int i = 0; i < MTILES * 4; i++)
        #pragma unroll
        for (int j = 0; j < 4; j++) acc[i][j] = 0.f;

    const int ntiles = K >> 4;
    stage(0, 0);
    stage(1, 1);

    for (int kt = 0; kt < ntiles; kt++) {
        const int p = kt % NST;
        if (kt < ntiles - 1) asm volatile("cp.async.wait_group 1;\n" ::);
        else                 asm volatile("cp.async.wait_group 0;\n" ::);
        __syncthreads();
        if (kt + 2 < ntiles) stage((kt + 2) % NST, kt + 2);

        uint32_t af[MTILES][4], bf[4][2];
        #pragma unroll
        for (int i = 0; i < MTILES; i++) {
            const int mr = wm * (MTILES * 16) + i * 16 + gid;
            af[i][0] = As[p][mr    ][tig];
            af[i][1] = As[p][mr + 8][tig];
            af[i][2] = As[p][mr    ][tig + 4];
            af[i][3] = As[p][mr + 8][tig + 4];
        }
        #pragma unroll
        for (int j = 0; j < 4; j++) {
            const int nc = wn * 32 + j * 8 + gid;
            bf[j][0] = Bs[p][tig    ][nc];
            bf[j][1] = Bs[p][tig + 4][nc];
        }
        #pragma unroll
        for (int i = 0; i < MTILES; i++)
            #pragma unroll
            for (int j = 0; j < 4; j++)
                mma16(acc[i * 4 + j], af[i], bf[j]);
        __syncthreads();
    }

    #pragma unroll
    for (int i = 0; i < MTILES; i++) {
        const int row = m0 + wm * (MTILES * 16) + i * 16 + gid;
        #pragma unroll
        for (int j = 0; j < 4; j++) {
            const int col = n0 + wn * 32 + j * 8 + tig * 2;
            float* Cp = C + (size_t)row * N + col;
            *(float2*)Cp = make_float2(acc[i * 4 + j][0], acc[i * 4 + j][1]);
            *(float2*)(Cp + (size_t)8 * N) = make_float2(acc[i * 4 + j][2], acc[i * 4 + j][3]);
        }
    }
}

// ---------------- depthwise causal conv v2: 4 timesteps/thread ----------
__global__ __launch_bounds__(256) void conv_silu_kernel(
    const float* __restrict__ xz, const float* __restrict__ cw,
    const float* __restrict__ cb, float* __restrict__ xc)
{
    int idx = blockIdx.x * 256 + threadIdx.x;      // over (NROWS/4)*DINNER
    if (idx >= (NROWS/4) * DINNER) return;
    const int d  = idx & (DINNER - 1);
    const int r4 = idx >> 10;
    const int l0 = (r4 << 2) & (LSEQ - 1);
    const int b  = (r4 << 2) >> 11;

    const float* col = xz + (size_t)(b * LSEQ) * XZCOLS + d;
    float v[7];
    #pragma unroll
    for (int k = 0; k < 7; k++) {
        int ll = l0 - 3 + k;
        v[k] = (ll >= 0) ? col[(size_t)ll * XZCOLS] : 0.f;
    }
    const float4 w = *(const float4*)(cw + d * 4);
    const float bias = cb[d];
    float* outp = xc + (size_t)(b * LSEQ + l0) * DINNER + d;
    #pragma unroll
    for (int i = 0; i < 4; i++) {
        float acc = bias + v[i] * w.x + v[i+1] * w.y + v[i+2] * w.z + v[i+3] * w.w;
        float sig = 1.f / (1.f + __expf(-acc));
        outp[(size_t)i * DINNER] = acc * sig;
    }
}

// ---------------- dbl = xc @ W_xproj : split-K x4 + atomics -------------
// grid (NROWS/16, 4), 256 thr. Block: 16 rows x 64 cols, K range 256.
#define DK 256
__global__ __launch_bounds__(256) void gemm_dbl_kernel(
    const float* __restrict__ X, const float* __restrict__ W,
    float* __restrict__ O)
{
    __shared__ float Xs[32][17];
    __shared__ float Ws[32][64];
    const int tid   = threadIdx.x;
    const int row0  = blockIdx.x * 16;
    const int kbase = blockIdx.y * DK;
    const int row = tid >> 4, c4 = (tid & 15) * 4;

    float acc[4] = {0.f, 0.f, 0.f, 0.f};

    for (int k0 = 0; k0 < DK; k0 += 32) {
        if (tid < 128) {
            int r = tid >> 3, cc = (tid & 7) * 4;
            float4 v = *(const float4*)(X + (size_t)(row0 + r) * DINNER + kbase + k0 + cc);
            Xs[cc+0][r] = v.x; Xs[cc+1][r] = v.y;
            Xs[cc+2][r] = v.z; Xs[cc+3][r] = v.w;
        }
        {
            int r = tid >> 4, cc = (tid & 15) * 4;
            *(float4*)&Ws[r][cc] =
                *(const float4*)(W + (size_t)(kbase + k0 + r) * 64 + cc);
            *(float4*)&Ws[r + 16][cc] =
                *(const float4*)(W + (size_t)(kbase + k0 + r + 16) * 64 + cc);
        }
        __syncthreads();
        #pragma unroll
        for (int kk = 0; kk < 32; kk++) {
            float a = Xs[kk][row];
            acc[0] += a * Ws[kk][c4+0];
            acc[1] += a * Ws[kk][c4+1];
            acc[2] += a * Ws[kk][c4+2];
            acc[3] += a * Ws[kk][c4+3];
        }
        __syncthreads();
    }

    float* Op = O + (size_t)(row0 + row) * DBLCOLS + c4;
    atomicAdd(Op + 0, acc[0]);
    atomicAdd(Op + 1, acc[1]);
    atomicAdd(Op + 2, acc[2]);
    atomicAdd(Op + 3, acc[3]);
}

// ---------------- dt = softplus(dtr @ W_dt + b_dt)  (K=32) --------------
__global__ __launch_bounds__(256) void dt_kernel(
    const float* __restrict__ dbl, const float* __restrict__ Wdt,
    const float* __restrict__ bdt, float* __restrict__ dt)
{
    __shared__ float dtr[8][32];
    const int tid = threadIdx.x;
    const int row0 = blockIdx.x * 8;
    {
        int r = tid >> 5, c = tid & 31;
        dtr[r][c] = dbl[(size_t)(row0 + r) * DBLCOLS + c];
    }
    __syncthreads();

    const int base = tid * 4;
    float4 bb = *(const float4*)(bdt + base);
    float acc[8][4];
    #pragma unroll
    for (int r = 0; r < 8; r++) {
        acc[r][0] = bb.x; acc[r][1] = bb.y; acc[r][2] = bb.z; acc[r][3] = bb.w;
    }
    #pragma unroll
    for (int k = 0; k < 32; k++) {
        float4 w = *(const float4*)(Wdt + (size_t)k * DINNER + base);
        #pragma unroll
        for (int r = 0; r < 8; r++) {
            float a = dtr[r][k];
            acc[r][0] += a * w.x; acc[r][1] += a * w.y;
            acc[r][2] += a * w.z; acc[r][3] += a * w.w;
        }
    }
    #pragma unroll
    for (int r = 0; r < 8; r++) {
        float o[4];
        #pragma unroll
        for (int j = 0; j < 4; j++) {
            float v = acc[r][j];
            o[j] = (v > 20.f) ? v : log1pf(__expf(v));
        }
        *(float4*)(dt + (size_t)(row0 + r) * DINNER + base) =
            make_float4(o[0], o[1], o[2], o[3]);
    }
}

// ---------------- selective scan v3: 8 lanes/channel, 2 states/lane -----
#define SCH 8
#define ST  64
#define NCHUNK (LSEQ/ST)

struct ScanBuf {
    float dt[ST][SCH];
    float xc[ST][SCH];
    float zz[ST][SCH];
    float bc[ST][2*DSTATE];
};

__global__ __launch_bounds__(64) void scan_kernel(
    const float* __restrict__ xz, const float* __restrict__ xc,
    const float* __restrict__ dbl, const float* __restrict__ dt,
    const float* __restrict__ A_log, const float* __restrict__ Dp,
    uint32_t* __restrict__ ybf)
{
    __shared__ ScanBuf sb[2];
    __shared__ float sy[ST][SCH];

    const int tid  = threadIdx.x;          // 0..63
    const int lane = tid & 31;
    const int w    = tid >> 5;
    const int sg   = lane & 7;             // state group: states 2sg, 2sg+1
    const int cl   = w * 4 + (lane >> 3);  // local channel 0..7
    const int chb  = blockIdx.x * SCH;
    const int b    = chb >> 10;
    const int d0   = chb & (DINNER - 1);
    const int d    = d0 + cl;
    const size_t rowb = (size_t)b * LSEQ;

    const float A0 = -__expf(A_log[d * DSTATE + 2*sg    ]);
    const float A1 = -__expf(A_log[d * DSTATE + 2*sg + 1]);
    const float Dd = Dp[d];

    auto prefetch = [&](int c, int pp) {
        const size_t r0 = rowb + (size_t)c * ST;
        #pragma unroll
        for (int j = 0; j < 2; j++) {
            int u = tid + j * 64;
            int rw = u >> 1, qq = (u & 1) * 4;
            cp16(s2u(&sb[pp].dt[rw][qq]), dt + (r0 + rw) * DINNER + d0 + qq);
            cp16(s2u(&sb[pp].xc[rw][qq]), xc + (r0 + rw) * DINNER + d0 + qq);
            cp16(s2u(&sb[pp].zz[rw][qq]), xz + (r0 + rw) * XZCOLS + DINNER + d0 + qq);
        }
        #pragma unroll
        for (int j = 0; j < 8; j++) {
            int u = tid + j * 64;
            int rw = u >> 3, qq = (u & 7) * 4;
            cp16(s2u(&sb[pp].bc[rw][qq]), dbl + (r0 + rw) * DBLCOLS + DTRANK + qq);
        }
        asm volatile("cp.async.commit_group;\n" ::);
    };

    prefetch(0, 0);
    prefetch(1, 1);

    float h0 = 0.f, h1 = 0.f;
    for (int c = 0; c < NCHUNK; c++) {
        const int p = c & 1;
        if (c < NCHUNK - 1) asm volatile("cp.async.wait_group 1;\n" ::);
        else                asm volatile("cp.async.wait_group 0;\n" ::);
        __syncthreads();

        #pragma unroll 8
        for (int t = 0; t < ST; t++) {
            float dtv = sb[p].dt[t][cl];
            float xv  = sb[p].xc[t][cl];
            float2 Bv = *(const float2*)&sb[p].bc[t][2*sg];
            float2 Cv = *(const float2*)&sb[p].bc[t][DSTATE + 2*sg];
            float e0 = __expf(dtv * A0);
            float e1 = __expf(dtv * A1);
            float dx = dtv * xv;
            h0 = h0 * e0 + dx * Bv.x;
            h1 = h1 * e1 + dx * Bv.y;
            float pr = h0 * Cv.x + h1 * Cv.y;
            pr += __shfl_xor_sync(0xffffffffu, pr, 4);
            pr += __shfl_xor_sync(0xffffffffu, pr, 2);
            pr += __shfl_xor_sync(0xffffffffu, pr, 1);
            if (sg == 0) sy[t][cl] = pr + xv * Dd;
        }
        __syncthreads();

        float2 yv[4], zv[4];
        #pragma unroll
        for (int j = 0; j < 4; j++) {
            int u = tid + j * 64;
            int rw = u >> 2, p2 = (u & 3) * 2;
            yv[j] = *(const float2*)&sy[rw][p2];
            zv[j] = *(const float2*)&sb[p].zz[rw][p2];
        }
        __syncthreads();
        if (c + 2 < NCHUNK) prefetch(c + 2, p);

        const size_t r0 = rowb + (size_t)c * ST;
        #pragma unroll
        for (int j = 0; j < 4; j++) {
            int u = tid + j * 64;
            int rw = u >> 2, pi = (u & 3);
            float s0 = zv[j].x / (1.f + __expf(-zv[j].x));
            float s1 = zv[j].y / (1.f + __expf(-zv[j].y));
            ybf[(r0 + rw) * (DINNER/2) + (d0 >> 1) + pi] =
                pack_bf2(yv[j].x * s0, yv[j].y * s1);
        }
    }
}

// ---------------- residual + LayerNorm ----------------------------------
__global__ __launch_bounds__(128) void ln_kernel(
    const float* __restrict__ go, const float* __restrict__ x,
    const float* __restrict__ gamma, const float* __restrict__ beta,
    float* __restrict__ out)
{
    const int row = blockIdx.x;
    const int tid = threadIdx.x;
    float4 a  = *(const float4*)(go + (size_t)row * DMODEL + tid * 4);
    float4 xr = *(const float4*)(x  + (size_t)row * DMODEL + tid * 4);
    float v0 = a.x + xr.x, v1 = a.y + xr.y, v2 = a.z + xr.z, v3 = a.w + xr.w;

    float s  = v0 + v1 + v2 + v3;
    float sq = v0*v0 + v1*v1 + v2*v2 + v3*v3;
    #pragma unroll
    for (int o = 16; o > 0; o >>= 1) {
        s  += __shfl_xor_sync(0xffffffffu, s,  o);
        sq += __shfl_xor_sync(0xffffffffu, sq, o);
    }
    __shared__ float ss[4], ssq[4];
    if ((tid & 31) == 0) { ss[tid >> 5] = s; ssq[tid >> 5] = sq; }
    __syncthreads();
    s  = ss[0]  + ss[1]  + ss[2]  + ss[3];
    sq = ssq[0] + ssq[1] + ssq[2] + ssq[3];

    const float mu  = s * (1.f / DMODEL);
    const float var = sq * (1.f / DMODEL) - mu * mu;
    const float inv = rsqrtf(var + 1e-5f);

    float4 g  = *(const float4*)(gamma + tid * 4);
    float4 be = *(const float4*)(beta  + tid * 4);
    float4 o;
    o.x = (v0 - mu) * inv * g.x + be.x;
    o.y = (v1 - mu) * inv * g.y + be.y;
    o.z = (v2 - mu) * inv * g.z + be.z;
    o.w = (v3 - mu) * inv * g.w + be.w;
    *(float4*)(out + (size_t)row * DMODEL + tid * 4) = o;
}

// ---------------- launcher ----------------------------------------------
extern "C" void kernel_launch(void* const* d_in, const int* in_sizes, int n_in,
                              void* d_out, int out_size)
{
    (void)in_sizes; (void)n_in; (void)out_size;
    const float* x      = (const float*)d_in[0];
    const float* W_in   = (const float*)d_in[1];
    const float* conv_w = (const float*)d_in[2];
    const float* conv_b = (const float*)d_in[3];
    const float* W_xprj = (const float*)d_in[4];
    const float* W_dt   = (const float*)d_in[5];
    const float* b_dt   = (const float*)d_in[6];
    const float* A_log  = (const float*)d_in[7];
    const float* Dvec   = (const float*)d_in[8];
    const float* W_out  = (const float*)d_in[9];
    const float* gamma  = (const float*)d_in[10];
    const float* beta   = (const float*)d_in[11];
    float* out = (float*)d_out;

    float *p_xz, *p_xc, *p_dbl, *p_dt, *p_o;
    uint32_t *p_xb, *p_ybf, *p_wpin, *p_wpout;
    cudaGetSymbolAddress((void**)&p_xz,    g_xz);
    cudaGetSymbolAddress((void**)&p_xc,    g_xc);
    cudaGetSymbolAddress((void**)&p_dbl,   g_dbl);
    cudaGetSymbolAddress((void**)&p_dt,    g_dt);
    cudaGetSymbolAddress((void**)&p_o,     g_o);
    cudaGetSymbolAddress((void**)&p_xb,    g_xb);
    cudaGetSymbolAddress((void**)&p_ybf,   g_ybf);
    cudaGetSymbolAddress((void**)&p_wpin,  g_wpin);
    cudaGetSymbolAddress((void**)&p_wpout, g_wpout);

    const int NCVT = NROWS*DMODEL/2 + (DMODEL/2)*XZCOLS + (DINNER/2)*DMODEL
                   + NROWS*DBLCOLS/4;

    // 0) pack x / W_in / W_out to bf16 layouts + zero dbl accumulator
    cvt_pack_kernel<<<(NCVT + 255) / 256, 256>>>(x, W_in, W_out, p_xb,
                                                 p_wpin, p_wpout, (float4*)p_dbl);
    // 1) xz = x @ W_in   (bf16 mma, pure cp.async operands)
    tmma_kernel<4><<<dim3(XZCOLS/128, NROWS/128), 256>>>(p_xb, p_wpin, p_xz, NROWS, XZCOLS, DMODEL);
    // 2) xc = silu(causal_conv(xi) + b)   (4 timesteps/thread)
    conv_silu_kernel<<<((NROWS/4)*DINNER)/256, 256>>>(p_xz, conv_w, conv_b, p_xc);
    // 3) dbl += xc @ W_xproj   (split-K x4, 1024 CTAs)
    gemm_dbl_kernel<<<dim3(NROWS/16, 4), 256>>>(p_xc, W_xprj, p_dbl);
    // 4) dt = softplus(dtr @ W_dt + b_dt)
    dt_kernel<<<NROWS/8, 256>>>(p_dbl, W_dt, b_dt, p_dt);
    // 5) selective scan (8 lanes/channel) -> y in bf16
    scan_kernel<<<(BATCH*DINNER)/SCH, 64>>>(p_xz, p_xc, p_dbl, p_dt, A_log, Dvec, p_ybf);
    // 6) o = y @ W_out   (bf16 mma, BM=64)
    tmma_kernel<2><<<dim3(DMODEL/128, NROWS/64), 256>>>(p_ybf, p_wpout, p_o, NROWS, DMODEL, DINNER);
    // 7) out = LN(o + x) * gamma + beta
    ln_kernel<<<NROWS, 128>>>(p_o, x, gamma, beta, out);
}

// round 15
// speedup vs baseline: 7.6405x; 1.0129x over previous
#include <cuda_runtime.h>
#include <cuda_bf16.h>
#include <math.h>
#include <stdint.h>

// ---------------- problem constants ----------------
#define BATCH   2
#define LSEQ    2048
#define DMODEL  512
#define DINNER  1024
#define DSTATE  16
#define DTRANK  32
#define NROWS   (BATCH*LSEQ)          // 4096
#define XZCOLS  (2*DINNER)            // 2048
#define DBLCOLS (DTRANK + 2*DSTATE)   // 64

// ---------------- scratch (device globals; no allocation) ----------------
__device__ float    g_xz [NROWS * XZCOLS];      // [xi | z]
__device__ float    g_xc [NROWS * DINNER];      // conv+silu output
__device__ float    g_dbl[NROWS * DBLCOLS];     // [dtr | B | C]
__device__ float    g_dt [NROWS * DINNER];      // softplus(dt)
__device__ float    g_o  [NROWS * DMODEL];      // pre-LN gemm output
__device__ uint32_t g_xb  [NROWS * DMODEL / 2];   // x as bf16 pairs (row-major)
__device__ uint32_t g_ybf [NROWS * DINNER / 2];   // y as bf16 pairs (row-major)
__device__ uint32_t g_wpin [(DMODEL/2) * XZCOLS]; // W_in  k-pair packed [K/2][N]
__device__ uint32_t g_wpout[(DINNER/2) * DMODEL]; // W_out k-pair packed [K/2][N]

// ---------------- helpers ----------------
__device__ __forceinline__ uint32_t s2u(const void* p) {
    uint32_t a;
    asm("{ .reg .u64 t; cvta.to.shared.u64 t, %1; cvt.u32.u64 %0, t; }"
        : "=r"(a) : "l"(p));
    return a;
}
__device__ __forceinline__ void cp16(uint32_t dst, const void* src) {
    asm volatile("cp.async.cg.shared.global [%0], [%1], 16;\n" :: "r"(dst), "l"(src));
}
// pack two fp32 -> bf16x2 (lo = first arg in low half)
__device__ __forceinline__ uint32_t pack_bf2(float lo, float hi) {
    uint32_t r;
    asm("cvt.rn.bf16x2.f32 %0, %1, %2;" : "=r"(r) : "f"(hi), "f"(lo));
    return r;
}
__device__ __forceinline__ void mma16(float* c, const uint32_t* a, const uint32_t* b) {
    asm volatile(
        "mma.sync.aligned.m16n8k16.row.col.f32.bf16.bf16.f32 "
        "{%0,%1,%2,%3}, {%4,%5,%6,%7}, {%8,%9}, {%0,%1,%2,%3};"
        : "+f"(c[0]), "+f"(c[1]), "+f"(c[2]), "+f"(c[3])
        : "r"(a[0]), "r"(a[1]), "r"(a[2]), "r"(a[3]), "r"(b[0]), "r"(b[1]));
}

// ---------------- cvt/pack: x/W -> bf16 layouts, zero dbl ---------------
__global__ __launch_bounds__(256) void cvt_pack_kernel(
    const float* __restrict__ x, const float* __restrict__ Win,
    const float* __restrict__ Wout, uint32_t* __restrict__ xb,
    uint32_t* __restrict__ wpin, uint32_t* __restrict__ wpout,
    float4* __restrict__ dblz)
{
    const int NX  = NROWS * DMODEL / 2;
    const int NWI = (DMODEL/2) * XZCOLS;
    const int NWO = (DINNER/2) * DMODEL;
    const int NZ  = NROWS * DBLCOLS / 4;
    int i = blockIdx.x * 256 + threadIdx.x;
    if (i < NX) {
        xb[i] = pack_bf2(x[2*i], x[2*i + 1]);
    } else if (i < NX + NWI) {
        int j = i - NX;
        int kp = j / XZCOLS, n = j - kp * XZCOLS;
        wpin[j] = pack_bf2(Win[(size_t)(2*kp) * XZCOLS + n],
                           Win[(size_t)(2*kp+1) * XZCOLS + n]);
    } else if (i < NX + NWI + NWO) {
        int j = i - NX - NWI;
        int kp = j / DMODEL, n = j - kp * DMODEL;
        wpout[j] = pack_bf2(Wout[(size_t)(2*kp) * DMODEL + n],
                            Wout[(size_t)(2*kp+1) * DMODEL + n]);
    } else if (i < NX + NWI + NWO + NZ) {
        dblz[i - NX - NWI - NWO] = make_float4(0.f, 0.f, 0.f, 0.f);
    }
}

// ---------------- bf16 tensor-core GEMM (pre-packed operands) -----------
// C[M,N] = A[M,K] @ B[K,N]. A: bf16 row-major as u32 k-pairs [M][K/2].
// B: k-pair packed u32 [K/2][N]. 3-stage cp.async pipeline, pure copies.
// Block tile (MTILES*32) x 128 x 16, 256 thr / 8 warps (2M x 4N).
template<int MTILES>
__global__ __launch_bounds__(256) void tmma_kernel(
    const uint32_t* __restrict__ A, const uint32_t* __restrict__ B,
    float* __restrict__ C, int M, int N, int K)
{
    constexpr int BM  = MTILES * 32;
    constexpr int NST = 3;
    __shared__ uint32_t As[NST][BM][12];   // cols 0..7 data, pad->12 (conflict-free)
    __shared__ uint32_t Bs[NST][8][136];

    const int tid  = threadIdx.x;
    const int wid  = tid >> 5, lane = tid & 31;
    const int gid  = lane >> 2, tig = lane & 3;
    const int wm   = wid & 1,  wn  = wid >> 1;     // 2 x 4 warp grid
    const int m0   = blockIdx.y * BM, n0 = blockIdx.x * 128;
    const int Ku   = K >> 1;                       // u32 per A row

    const int arow = tid >> 1, ahalf = (tid & 1) * 4;
    const int kp = tid >> 5, nq = (tid & 31) * 4;

    const uint32_t* Aptr = A + (size_t)(m0 + arow) * Ku + ahalf;
    const uint32_t* Bptr = B + (size_t)kp * N + n0 + nq;

    auto stage = [&](int s, int kt) {
        if (MTILES == 4 || tid < 128)
            cp16(s2u(&As[s][arow][ahalf]), Aptr + kt * 8);
        cp16(s2u(&Bs[s][kp][nq]), Bptr + (size_t)(kt * 8) * N);
        asm volatile("cp.async.commit_group;\n" ::);
    };

    float acc[MTILES * 4][4];
    #pragma unroll
    for (int i = 0; i < MTILES * 4; i++)
        #pragma unroll
        for (int j = 0; j < 4; j++) acc[i][j] = 0.f;

    const int ntiles = K >> 4;
    stage(0, 0);
    stage(1, 1);

    for (int kt = 0; kt < ntiles; kt++) {
        const int p = kt % NST;
        if (kt < ntiles - 1) asm volatile("cp.async.wait_group 1;\n" ::);
        else                 asm volatile("cp.async.wait_group 0;\n" ::);
        __syncthreads();
        if (kt + 2 < ntiles) stage((kt + 2) % NST, kt + 2);

        uint32_t af[MTILES][4], bf[4][2];
        #pragma unroll
        for (int i = 0; i < MTILES; i++) {
            const int mr = wm * (MTILES * 16) + i * 16 + gid;
            af[i][0] = As[p][mr    ][tig];
            af[i][1] = As[p][mr + 8][tig];
            af[i][2] = As[p][mr    ][tig + 4];
            af[i][3] = As[p][mr + 8][tig + 4];
        }
        #pragma unroll
        for (int j = 0; j < 4; j++) {
            const int nc = wn * 32 + j * 8 + gid;
            bf[j][0] = Bs[p][tig    ][nc];
            bf[j][1] = Bs[p][tig + 4][nc];
        }
        #pragma unroll
        for (int i = 0; i < MTILES; i++)
            #pragma unroll
            for (int j = 0; j < 4; j++)
                mma16(acc[i * 4 + j], af[i], bf[j]);
        __syncthreads();
    }

    #pragma unroll
    for (int i = 0; i < MTILES; i++) {
        const int row = m0 + wm * (MTILES * 16) + i * 16 + gid;
        #pragma unroll
        for (int j = 0; j < 4; j++) {
            const int col = n0 + wn * 32 + j * 8 + tig * 2;
            float* Cp = C + (size_t)row * N + col;
            *(float2*)Cp = make_float2(acc[i * 4 + j][0], acc[i * 4 + j][1]);
            *(float2*)(Cp + (size_t)8 * N) = make_float2(acc[i * 4 + j][2], acc[i * 4 + j][3]);
        }
    }
}

// ---------------- depthwise causal conv v2: 4 timesteps/thread ----------
__global__ __launch_bounds__(256) void conv_silu_kernel(
    const float* __restrict__ xz, const float* __restrict__ cw,
    const float* __restrict__ cb, float* __restrict__ xc)
{
    int idx = blockIdx.x * 256 + threadIdx.x;      // over (NROWS/4)*DINNER
    if (idx >= (NROWS/4) * DINNER) return;
    const int d  = idx & (DINNER - 1);
    const int r4 = idx >> 10;
    const int l0 = (r4 << 2) & (LSEQ - 1);
    const int b  = (r4 << 2) >> 11;

    const float* col = xz + (size_t)(b * LSEQ) * XZCOLS + d;
    float v[7];
    #pragma unroll
    for (int k = 0; k < 7; k++) {
        int ll = l0 - 3 + k;
        v[k] = (ll >= 0) ? col[(size_t)ll * XZCOLS] : 0.f;
    }
    const float4 w = *(const float4*)(cw + d * 4);
    const float bias = cb[d];
    float* outp = xc + (size_t)(b * LSEQ + l0) * DINNER + d;
    #pragma unroll
    for (int i = 0; i < 4; i++) {
        float acc = bias + v[i] * w.x + v[i+1] * w.y + v[i+2] * w.z + v[i+3] * w.w;
        float sig = 1.f / (1.f + __expf(-acc));
        outp[(size_t)i * DINNER] = acc * sig;
    }
}

// ---------------- dbl = xc @ W_xproj : split-K x4, vectorized LDS -------
// grid (NROWS/16, 4), 256 thr. Block: 16 rows x 64 cols, K range 256.
// Xs kept k-major [16][36] so both Xs and Ws inner reads are LDS.128:
// per 4 k-steps: 1 LDS.128 (Xs) + 4 LDS.128 (Ws) feed 16 FFMA.
#define DK 256
__global__ __launch_bounds__(256) void gemm_dbl_kernel(
    const float* __restrict__ X, const float* __restrict__ W,
    float* __restrict__ O)
{
    __shared__ float Xs[16][36];
    __shared__ float Ws[32][64];
    const int tid   = threadIdx.x;
    const int row0  = blockIdx.x * 16;
    const int kbase = blockIdx.y * DK;
    const int row = tid >> 4, c4 = (tid & 15) * 4;

    float acc[4] = {0.f, 0.f, 0.f, 0.f};

    for (int k0 = 0; k0 < DK; k0 += 32) {
        if (tid < 128) {
            int r = tid >> 3, cc = (tid & 7) * 4;
            *(float4*)&Xs[r][cc] =
                *(const float4*)(X + (size_t)(row0 + r) * DINNER + kbase + k0 + cc);
        }
        {
            int r = tid >> 4, cc = (tid & 15) * 4;
            *(float4*)&Ws[r][cc] =
                *(const float4*)(W + (size_t)(kbase + k0 + r) * 64 + cc);
            *(float4*)&Ws[r + 16][cc] =
                *(const float4*)(W + (size_t)(kbase + k0 + r + 16) * 64 + cc);
        }
        __syncthreads();
        #pragma unroll
        for (int kk = 0; kk < 32; kk += 4) {
            float4 a  = *(const float4*)&Xs[row][kk];
            float4 w0 = *(const float4*)&Ws[kk + 0][c4];
            float4 w1 = *(const float4*)&Ws[kk + 1][c4];
            float4 w2 = *(const float4*)&Ws[kk + 2][c4];
            float4 w3 = *(const float4*)&Ws[kk + 3][c4];
            acc[0] += a.x * w0.x + a.y * w1.x + a.z * w2.x + a.w * w3.x;
            acc[1] += a.x * w0.y + a.y * w1.y + a.z * w2.y + a.w * w3.y;
            acc[2] += a.x * w0.z + a.y * w1.z + a.z * w2.z + a.w * w3.z;
            acc[3] += a.x * w0.w + a.y * w1.w + a.z * w2.w + a.w * w3.w;
        }
        __syncthreads();
    }

    float* Op = O + (size_t)(row0 + row) * DBLCOLS + c4;
    atomicAdd(Op + 0, acc[0]);
    atomicAdd(Op + 1, acc[1]);
    atomicAdd(Op + 2, acc[2]);
    atomicAdd(Op + 3, acc[3]);
}

// ---------------- dt = softplus(dtr @ W_dt + b_dt)  (K=32) --------------
__global__ __launch_bounds__(256) void dt_kernel(
    const float* __restrict__ dbl, const float* __restrict__ Wdt,
    const float* __restrict__ bdt, float* __restrict__ dt)
{
    __shared__ float dtr[8][32];
    const int tid = threadIdx.x;
    const int row0 = blockIdx.x * 8;
    {
        int r = tid >> 5, c = tid & 31;
        dtr[r][c] = dbl[(size_t)(row0 + r) * DBLCOLS + c];
    }
    __syncthreads();

    const int base = tid * 4;
    float4 bb = *(const float4*)(bdt + base);
    float acc[8][4];
    #pragma unroll
    for (int r = 0; r < 8; r++) {
        acc[r][0] = bb.x; acc[r][1] = bb.y; acc[r][2] = bb.z; acc[r][3] = bb.w;
    }
    #pragma unroll
    for (int k = 0; k < 32; k++) {
        float4 w = *(const float4*)(Wdt + (size_t)k * DINNER + base);
        #pragma unroll
        for (int r = 0; r < 8; r++) {
            float a = dtr[r][k];
            acc[r][0] += a * w.x; acc[r][1] += a * w.y;
            acc[r][2] += a * w.z; acc[r][3] += a * w.w;
        }
    }
    #pragma unroll
    for (int r = 0; r < 8; r++) {
        float o[4];
        #pragma unroll
        for (int j = 0; j < 4; j++) {
            float v = acc[r][j];
            o[j] = (v > 20.f) ? v : log1pf(__expf(v));
        }
        *(float4*)(dt + (size_t)(row0 + r) * DINNER + base) =
            make_float4(o[0], o[1], o[2], o[3]);
    }
}

// ---------------- selective scan v3: 8 lanes/channel, 2 states/lane -----
#define SCH 8
#define ST  64
#define NCHUNK (LSEQ/ST)

struct ScanBuf {
    float dt[ST][SCH];
    float xc[ST][SCH];
    float zz[ST][SCH];
    float bc[ST][2*DSTATE];
};

__global__ __launch_bounds__(64) void scan_kernel(
    const float* __restrict__ xz, const float* __restrict__ xc,
    const float* __restrict__ dbl, const float* __restrict__ dt,
    const float* __restrict__ A_log, const float* __restrict__ Dp,
    uint32_t* __restrict__ ybf)
{
    __shared__ ScanBuf sb[2];
    __shared__ float sy[ST][SCH];

    const int tid  = threadIdx.x;          // 0..63
    const int lane = tid & 31;
    const int w    = tid >> 5;
    const int sg   = lane & 7;             // state group: states 2sg, 2sg+1
    const int cl   = w * 4 + (lane >> 3);  // local channel 0..7
    const int chb  = blockIdx.x * SCH;
    const int b    = chb >> 10;
    const int d0   = chb & (DINNER - 1);
    const int d    = d0 + cl;
    const size_t rowb = (size_t)b * LSEQ;

    const float A0 = -__expf(A_log[d * DSTATE + 2*sg    ]);
    const float A1 = -__expf(A_log[d * DSTATE + 2*sg + 1]);
    const float Dd = Dp[d];

    auto prefetch = [&](int c, int pp) {
        const size_t r0 = rowb + (size_t)c * ST;
        #pragma unroll
        for (int j = 0; j < 2; j++) {
            int u = tid + j * 64;
            int rw = u >> 1, qq = (u & 1) * 4;
            cp16(s2u(&sb[pp].dt[rw][qq]), dt + (r0 + rw) * DINNER + d0 + qq);
            cp16(s2u(&sb[pp].xc[rw][qq]), xc + (r0 + rw) * DINNER + d0 + qq);
            cp16(s2u(&sb[pp].zz[rw][qq]), xz + (r0 + rw) * XZCOLS + DINNER + d0 + qq);
        }
        #pragma unroll
        for (int j = 0; j < 8; j++) {
            int u = tid + j * 64;
            int rw = u >> 3, qq = (u & 7) * 4;
            cp16(s2u(&sb[pp].bc[rw][qq]), dbl + (r0 + rw) * DBLCOLS + DTRANK + qq);
        }
        asm volatile("cp.async.commit_group;\n" ::);
    };

    prefetch(0, 0);
    prefetch(1, 1);

    float h0 = 0.f, h1 = 0.f;
    for (int c = 0; c < NCHUNK; c++) {
        const int p = c & 1;
        if (c < NCHUNK - 1) asm volatile("cp.async.wait_group 1;\n" ::);
        else                asm volatile("cp.async.wait_group 0;\n" ::);
        __syncthreads();

        #pragma unroll 8
        for (int t = 0; t < ST; t++) {
            float dtv = sb[p].dt[t][cl];
            float xv  = sb[p].xc[t][cl];
            float2 Bv = *(const float2*)&sb[p].bc[t][2*sg];
            float2 Cv = *(const float2*)&sb[p].bc[t][DSTATE + 2*sg];
            float e0 = __expf(dtv * A0);
            float e1 = __expf(dtv * A1);
            float dx = dtv * xv;
            h0 = h0 * e0 + dx * Bv.x;
            h1 = h1 * e1 + dx * Bv.y;
            float pr = h0 * Cv.x + h1 * Cv.y;
            pr += __shfl_xor_sync(0xffffffffu, pr, 4);
            pr += __shfl_xor_sync(0xffffffffu, pr, 2);
            pr += __shfl_xor_sync(0xffffffffu, pr, 1);
            if (sg == 0) sy[t][cl] = pr + xv * Dd;
        }
        __syncthreads();

        float2 yv[4], zv[4];
        #pragma unroll
        for (int j = 0; j < 4; j++) {
            int u = tid + j * 64;
            int rw = u >> 2, p2 = (u & 3) * 2;
            yv[j] = *(const float2*)&sy[rw][p2];
            zv[j] = *(const float2*)&sb[p].zz[rw][p2];
        }
        __syncthreads();
        if (c + 2 < NCHUNK) prefetch(c + 2, p);

        const size_t r0 = rowb + (size_t)c * ST;
        #pragma unroll
        for (int j = 0; j < 4; j++) {
            int u = tid + j * 64;
            int rw = u >> 2, pi = (u & 3);
            float s0 = zv[j].x / (1.f + __expf(-zv[j].x));
            float s1 = zv[j].y / (1.f + __expf(-zv[j].y));
            ybf[(r0 + rw) * (DINNER/2) + (d0 >> 1) + pi] =
                pack_bf2(yv[j].x * s0, yv[j].y * s1);
        }
    }
}

// ---------------- residual + LayerNorm ----------------------------------
__global__ __launch_bounds__(128) void ln_kernel(
    const float* __restrict__ go, const float* __restrict__ x,
    const float* __restrict__ gamma, const float* __restrict__ beta,
    float* __restrict__ out)
{
    const int row = blockIdx.x;
    const int tid = threadIdx.x;
    float4 a  = *(const float4*)(go + (size_t)row * DMODEL + tid * 4);
    float4 xr = *(const float4*)(x  + (size_t)row * DMODEL + tid * 4);
    float v0 = a.x + xr.x, v1 = a.y + xr.y, v2 = a.z + xr.z, v3 = a.w + xr.w;

    float s  = v0 + v1 + v2 + v3;
    float sq = v0*v0 + v1*v1 + v2*v2 + v3*v3;
    #pragma unroll
    for (int o = 16; o > 0; o >>= 1) {
        s  += __shfl_xor_sync(0xffffffffu, s,  o);
        sq += __shfl_xor_sync(0xffffffffu, sq, o);
    }
    __shared__ float ss[4], ssq[4];
    if ((tid & 31) == 0) { ss[tid >> 5] = s; ssq[tid >> 5] = sq; }
    __syncthreads();
    s  = ss[0]  + ss[1]  + ss[2]  + ss[3];
    sq = ssq[0] + ssq[1] + ssq[2] + ssq[3];

    const float mu  = s * (1.f / DMODEL);
    const float var = sq * (1.f / DMODEL) - mu * mu;
    const float inv = rsqrtf(var + 1e-5f);

    float4 g  = *(const float4*)(gamma + tid * 4);
    float4 be = *(const float4*)(beta  + tid * 4);
    float4 o;
    o.x = (v0 - mu) * inv * g.x + be.x;
    o.y = (v1 - mu) * inv * g.y + be.y;
    o.z = (v2 - mu) * inv * g.z + be.z;
    o.w = (v3 - mu) * inv * g.w + be.w;
    *(float4*)(out + (size_t)row * DMODEL + tid * 4) = o;
}

// ---------------- launcher ----------------------------------------------
extern "C" void kernel_launch(void* const* d_in, const int* in_sizes, int n_in,
                              void* d_out, int out_size)
{
    (void)in_sizes; (void)n_in; (void)out_size;
    const float* x      = (const float*)d_in[0];
    const float* W_in   = (const float*)d_in[1];
    const float* conv_w = (const float*)d_in[2];
    const float* conv_b = (const float*)d_in[3];
    const float* W_xprj = (const float*)d_in[4];
    const float* W_dt   = (const float*)d_in[5];
    const float* b_dt   = (const float*)d_in[6];
    const float* A_log  = (const float*)d_in[7];
    const float* Dvec   = (const float*)d_in[8];
    const float* W_out  = (const float*)d_in[9];
    const float* gamma  = (const float*)d_in[10];
    const float* beta   = (const float*)d_in[11];
    float* out = (float*)d_out;

    float *p_xz, *p_xc, *p_dbl, *p_dt, *p_o;
    uint32_t *p_xb, *p_ybf, *p_wpin, *p_wpout;
    cudaGetSymbolAddress((void**)&p_xz,    g_xz);
    cudaGetSymbolAddress((void**)&p_xc,    g_xc);
    cudaGetSymbolAddress((void**)&p_dbl,   g_dbl);
    cudaGetSymbolAddress((void**)&p_dt,    g_dt);
    cudaGetSymbolAddress((void**)&p_o,     g_o);
    cudaGetSymbolAddress((void**)&p_xb,    g_xb);
    cudaGetSymbolAddress((void**)&p_ybf,   g_ybf);
    cudaGetSymbolAddress((void**)&p_wpin,  g_wpin);
    cudaGetSymbolAddress((void**)&p_wpout, g_wpout);

    const int NCVT = NROWS*DMODEL/2 + (DMODEL/2)*XZCOLS + (DINNER/2)*DMODEL
                   + NROWS*DBLCOLS/4;

    // 0) pack x / W_in / W_out to bf16 layouts + zero dbl accumulator
    cvt_pack_kernel<<<(NCVT + 255) / 256, 256>>>(x, W_in, W_out, p_xb,
                                                 p_wpin, p_wpout, (float4*)p_dbl);
    // 1) xz = x @ W_in   (bf16 mma, pure cp.async operands)
    tmma_kernel<4><<<dim3(XZCOLS/128, NROWS/128), 256>>>(p_xb, p_wpin, p_xz, NROWS, XZCOLS, DMODEL);
    // 2) xc = silu(causal_conv(xi) + b)   (4 timesteps/thread)
    conv_silu_kernel<<<((NROWS/4)*DINNER)/256, 256>>>(p_xz, conv_w, conv_b, p_xc);
    // 3) dbl += xc @ W_xproj   (split-K x4, vectorized LDS)
    gemm_dbl_kernel<<<dim3(NROWS/16, 4), 256>>>(p_xc, W_xprj, p_dbl);
    // 4) dt = softplus(dtr @ W_dt + b_dt)
    dt_kernel<<<NROWS/8, 256>>>(p_dbl, W_dt, b_dt, p_dt);
    // 5) selective scan (8 lanes/channel) -> y in bf16
    scan_kernel<<<(BATCH*DINNER)/SCH, 64>>>(p_xz, p_xc, p_dbl, p_dt, A_log, Dvec, p_ybf);
    // 6) o = y @ W_out   (bf16 mma, BM=64)
    tmma_kernel<2><<<dim3(DMODEL/128, NROWS/64), 256>>>(p_ybf, p_wpout, p_o, NROWS, DMODEL, DINNER);
    // 7) out = LN(o + x) * gamma + beta
    ln_kernel<<<NROWS, 128>>>(p_o, x, gamma, beta, out);
}

// round 16
// speedup vs baseline: 8.3859x; 1.0976x over previous
#include <cuda_runtime.h>
#include <cuda_bf16.h>
#include <math.h>
#include <stdint.h>

// ---------------- problem constants ----------------
#define BATCH   2
#define LSEQ    2048
#define DMODEL  512
#define DINNER  1024
#define DSTATE  16
#define DTRANK  32
#define NROWS   (BATCH*LSEQ)          // 4096
#define XZCOLS  (2*DINNER)            // 2048
#define DBLCOLS (DTRANK + 2*DSTATE)   // 64

// ---------------- scratch (device globals; no allocation) ----------------
__device__ float    g_xz [NROWS * XZCOLS];      // [xi | z]
__device__ float    g_xc [NROWS * DINNER];      // conv+silu output (fp32, scan)
__device__ __nv_bfloat16 g_xcb[NROWS * DINNER]; // conv+silu output (bf16, dbl GEMM)
__device__ float    g_dbl[NROWS * DBLCOLS];     // [dtr | B | C]
__device__ float    g_dt [NROWS * DINNER];      // softplus(dt)
__device__ float    g_o  [NROWS * DMODEL];      // pre-LN gemm output
__device__ uint32_t g_xb  [NROWS * DMODEL / 2];   // x as bf16 pairs (row-major)
__device__ uint32_t g_ybf [NROWS * DINNER / 2];   // y as bf16 pairs (row-major)
__device__ uint32_t g_wpin [(DMODEL/2) * XZCOLS]; // W_in   k-pair packed [K/2][N]
__device__ uint32_t g_wpout[(DINNER/2) * DMODEL]; // W_out  k-pair packed [K/2][N]
__device__ uint32_t g_wpx  [(DINNER/2) * DBLCOLS];// W_xprj k-pair packed [K/2][64]

// ---------------- helpers ----------------
__device__ __forceinline__ uint32_t s2u(const void* p) {
    uint32_t a;
    asm("{ .reg .u64 t; cvta.to.shared.u64 t, %1; cvt.u32.u64 %0, t; }"
        : "=r"(a) : "l"(p));
    return a;
}
__device__ __forceinline__ void cp16(uint32_t dst, const void* src) {
    asm volatile("cp.async.cg.shared.global [%0], [%1], 16;\n" :: "r"(dst), "l"(src));
}
// pack two fp32 -> bf16x2 (lo = first arg in low half)
__device__ __forceinline__ uint32_t pack_bf2(float lo, float hi) {
    uint32_t r;
    asm("cvt.rn.bf16x2.f32 %0, %1, %2;" : "=r"(r) : "f"(hi), "f"(lo));
    return r;
}
__device__ __forceinline__ void mma16(float* c, const uint32_t* a, const uint32_t* b) {
    asm volatile(
        "mma.sync.aligned.m16n8k16.row.col.f32.bf16.bf16.f32 "
        "{%0,%1,%2,%3}, {%4,%5,%6,%7}, {%8,%9}, {%0,%1,%2,%3};"
        : "+f"(c[0]), "+f"(c[1]), "+f"(c[2]), "+f"(c[3])
        : "r"(a[0]), "r"(a[1]), "r"(a[2]), "r"(a[3]), "r"(b[0]), "r"(b[1]));
}

// ---------------- cvt/pack: x/W_in/W_out/W_xproj -> bf16, zero dbl ------
__global__ __launch_bounds__(256) void cvt_pack_kernel(
    const float* __restrict__ x, const float* __restrict__ Win,
    const float* __restrict__ Wout, const float* __restrict__ Wx,
    uint32_t* __restrict__ xb, uint32_t* __restrict__ wpin,
    uint32_t* __restrict__ wpout, uint32_t* __restrict__ wpx,
    float4* __restrict__ dblz)
{
    const int NX  = NROWS * DMODEL / 2;
    const int NWI = (DMODEL/2) * XZCOLS;
    const int NWO = (DINNER/2) * DMODEL;
    const int NWX = (DINNER/2) * DBLCOLS;
    const int NZ  = NROWS * DBLCOLS / 4;
    int i = blockIdx.x * 256 + threadIdx.x;
    if (i < NX) {
        xb[i] = pack_bf2(x[2*i], x[2*i + 1]);
    } else if (i < NX + NWI) {
        int j = i - NX;
        int kp = j / XZCOLS, n = j - kp * XZCOLS;
        wpin[j] = pack_bf2(Win[(size_t)(2*kp) * XZCOLS + n],
                           Win[(size_t)(2*kp+1) * XZCOLS + n]);
    } else if (i < NX + NWI + NWO) {
        int j = i - NX - NWI;
        int kp = j / DMODEL, n = j - kp * DMODEL;
        wpout[j] = pack_bf2(Wout[(size_t)(2*kp) * DMODEL + n],
                            Wout[(size_t)(2*kp+1) * DMODEL + n]);
    } else if (i < NX + NWI + NWO + NWX) {
        int j = i - NX - NWI - NWO;
        int kp = j >> 6, n = j & 63;
        wpx[j] = pack_bf2(Wx[(size_t)(2*kp) * DBLCOLS + n],
                          Wx[(size_t)(2*kp+1) * DBLCOLS + n]);
    } else if (i < NX + NWI + NWO + NWX + NZ) {
        dblz[i - NX - NWI - NWO - NWX] = make_float4(0.f, 0.f, 0.f, 0.f);
    }
}

// ---------------- bf16 tensor-core GEMM (pre-packed operands) -----------
// C[M,N] = A[M,K] @ B[K,N]. A: bf16 row-major as u32 k-pairs [M][K/2].
// B: k-pair packed u32 [K/2][N]. 3-stage cp.async pipeline, pure copies.
// Block tile (MTILES*32) x 128 x 16, 256 thr / 8 warps (2M x 4N).
template<int MTILES>
__global__ __launch_bounds__(256) void tmma_kernel(
    const uint32_t* __restrict__ A, const uint32_t* __restrict__ B,
    float* __restrict__ C, int M, int N, int K)
{
    constexpr int BM  = MTILES * 32;
    constexpr int NST = 3;
    __shared__ uint32_t As[NST][BM][12];   // cols 0..7 data, pad->12 (conflict-free)
    __shared__ uint32_t Bs[NST][8][136];

    const int tid  = threadIdx.x;
    const int wid  = tid >> 5, lane = tid & 31;
    const int gid  = lane >> 2, tig = lane & 3;
    const int wm   = wid & 1,  wn  = wid >> 1;     // 2 x 4 warp grid
    const int m0   = blockIdx.y * BM, n0 = blockIdx.x * 128;
    const int Ku   = K >> 1;                       // u32 per A row

    const int arow = tid >> 1, ahalf = (tid & 1) * 4;
    const int kp = tid >> 5, nq = (tid & 31) * 4;

    const uint32_t* Aptr = A + (size_t)(m0 + arow) * Ku + ahalf;
    const uint32_t* Bptr = B + (size_t)kp * N + n0 + nq;

    auto stage = [&](int s, int kt) {
        if (MTILES == 4 || tid < 128)
            cp16(s2u(&As[s][arow][ahalf]), Aptr + kt * 8);
        cp16(s2u(&Bs[s][kp][nq]), Bptr + (size_t)(kt * 8) * N);
        asm volatile("cp.async.commit_group;\n" ::);
    };

    float acc[MTILES * 4][4];
    #pragma unroll
    for (int i = 0; i < MTILES * 4; i++)
        #pragma unroll
        for (int j = 0; j < 4; j++) acc[i][j] = 0.f;

    const int ntiles = K >> 4;
    stage(0, 0);
    stage(1, 1);

    for (int kt = 0; kt < ntiles; kt++) {
        const int p = kt % NST;
        if (kt < ntiles - 1) asm volatile("cp.async.wait_group 1;\n" ::);
        else                 asm volatile("cp.async.wait_group 0;\n" ::);
        __syncthreads();
        if (kt + 2 < ntiles) stage((kt + 2) % NST, kt + 2);

        uint32_t af[MTILES][4], bf[4][2];
        #pragma unroll
        for (int i = 0; i < MTILES; i++) {
            const int mr = wm * (MTILES * 16) + i * 16 + gid;
            af[i][0] = As[p][mr    ][tig];
            af[i][1] = As[p][mr + 8][tig];
            af[i][2] = As[p][mr    ][tig + 4];
            af[i][3] = As[p][mr + 8][tig + 4];
        }
        #pragma unroll
        for (int j = 0; j < 4; j++) {
            const int nc = wn * 32 + j * 8 + gid;
            bf[j][0] = Bs[p][tig    ][nc];
            bf[j][1] = Bs[p][tig + 4][nc];
        }
        #pragma unroll
        for (int i = 0; i < MTILES; i++)
            #pragma unroll
            for (int j = 0; j < 4; j++)
                mma16(acc[i * 4 + j], af[i], bf[j]);
        __syncthreads();
    }

    #pragma unroll
    for (int i = 0; i < MTILES; i++) {
        const int row = m0 + wm * (MTILES * 16) + i * 16 + gid;
        #pragma unroll
        for (int j = 0; j < 4; j++) {
            const int col = n0 + wn * 32 + j * 8 + tig * 2;
            float* Cp = C + (size_t)row * N + col;
            *(float2*)Cp = make_float2(acc[i * 4 + j][0], acc[i * 4 + j][1]);
            *(float2*)(Cp + (size_t)8 * N) = make_float2(acc[i * 4 + j][2], acc[i * 4 + j][3]);
        }
    }
}

// ---------------- dbl = xc @ W_xproj : bf16 mma, split-K x4 -------------
// Block tile 64x64, 8 warps (4M x 2N), warp tile 16x32, K=256 per split.
// fp32 atomicAdd epilogue into pre-zeroed dbl. Grid (NROWS/64, 4).
__global__ __launch_bounds__(256) void tmma_dbl_kernel(
    const uint32_t* __restrict__ A,   // xc bf16 pairs [NROWS][DINNER/2]
    const uint32_t* __restrict__ B,   // W_xproj packed [DINNER/2][64]
    float* __restrict__ O)
{
    constexpr int NST = 3;
    __shared__ uint32_t As[NST][64][12];
    __shared__ uint32_t Bs[NST][8][72];

    const int tid = threadIdx.x;
    const int wid = tid >> 5, lane = tid & 31;
    const int gid = lane >> 2, tig = lane & 3;
    const int wm = wid & 3, wn = wid >> 2;      // 4M x 2N
    const int m0 = blockIdx.x * 64;
    const int kp0 = blockIdx.y * 128;           // k-pair base (256 floats)
    const int Ku = DINNER >> 1;                 // 512 u32 per A row

    const int arow = (tid & 127) >> 1, ahalf = (tid & 1) * 4;
    const int kpr  = (tid & 127) >> 4, nq = (tid & 15) * 4;

    const uint32_t* Aptr = A + (size_t)(m0 + arow) * Ku + kp0 + ahalf;
    const uint32_t* Bptr = B + (size_t)(kp0 + kpr) * 64 + nq;

    auto stage = [&](int s, int kt) {
        if (tid < 128) {
            cp16(s2u(&As[s][arow][ahalf]), Aptr + kt * 8);
            cp16(s2u(&Bs[s][kpr][nq]), Bptr + (size_t)(kt * 8) * 64);
        }
        asm volatile("cp.async.commit_group;\n" ::);
    };

    float acc[4][4];
    #pragma unroll
    for (int j = 0; j < 4; j++)
        #pragma unroll
        for (int q = 0; q < 4; q++) acc[j][q] = 0.f;

    const int ntiles = 16;                      // 256 / 16
    stage(0, 0);
    stage(1, 1);

    for (int kt = 0; kt < ntiles; kt++) {
        const int p = kt % NST;
        if (kt < ntiles - 1) asm volatile("cp.async.wait_group 1;\n" ::);
        else                 asm volatile("cp.async.wait_group 0;\n" ::);
        __syncthreads();
        if (kt + 2 < ntiles) stage((kt + 2) % NST, kt + 2);

        uint32_t af[4], bf[4][2];
        const int mr = wm * 16 + gid;
        af[0] = As[p][mr    ][tig];
        af[1] = As[p][mr + 8][tig];
        af[2] = As[p][mr    ][tig + 4];
        af[3] = As[p][mr + 8][tig + 4];
        #pragma unroll
        for (int j = 0; j < 4; j++) {
            const int nc = wn * 32 + j * 8 + gid;
            bf[j][0] = Bs[p][tig    ][nc];
            bf[j][1] = Bs[p][tig + 4][nc];
        }
        #pragma unroll
        for (int j = 0; j < 4; j++)
            mma16(acc[j], af, bf[j]);
        __syncthreads();
    }

    const int row = m0 + wm * 16 + gid;
    #pragma unroll
    for (int j = 0; j < 4; j++) {
        const int col = wn * 32 + j * 8 + tig * 2;
        float* Op = O + (size_t)row * DBLCOLS + col;
        atomicAdd(Op,     acc[j][0]);
        atomicAdd(Op + 1, acc[j][1]);
        float* Oq = O + (size_t)(row + 8) * DBLCOLS + col;
        atomicAdd(Oq,     acc[j][2]);
        atomicAdd(Oq + 1, acc[j][3]);
    }
}

// ---------------- depthwise causal conv v2: 4 timesteps/thread ----------
__global__ __launch_bounds__(256) void conv_silu_kernel(
    const float* __restrict__ xz, const float* __restrict__ cw,
    const float* __restrict__ cb, float* __restrict__ xc,
    __nv_bfloat16* __restrict__ xcb)
{
    int idx = blockIdx.x * 256 + threadIdx.x;      // over (NROWS/4)*DINNER
    if (idx >= (NROWS/4) * DINNER) return;
    const int d  = idx & (DINNER - 1);
    const int r4 = idx >> 10;
    const int l0 = (r4 << 2) & (LSEQ - 1);
    const int b  = (r4 << 2) >> 11;

    const float* col = xz + (size_t)(b * LSEQ) * XZCOLS + d;
    float v[7];
    #pragma unroll
    for (int k = 0; k < 7; k++) {
        int ll = l0 - 3 + k;
        v[k] = (ll >= 0) ? col[(size_t)ll * XZCOLS] : 0.f;
    }
    const float4 w = *(const float4*)(cw + d * 4);
    const float bias = cb[d];
    const size_t base = (size_t)(b * LSEQ + l0) * DINNER + d;
    #pragma unroll
    for (int i = 0; i < 4; i++) {
        float acc = bias + v[i] * w.x + v[i+1] * w.y + v[i+2] * w.z + v[i+3] * w.w;
        float sig = 1.f / (1.f + __expf(-acc));
        float r = acc * sig;
        xc [base + (size_t)i * DINNER] = r;
        xcb[base + (size_t)i * DINNER] = __float2bfloat16(r);
    }
}

// ---------------- dt = softplus(dtr @ W_dt + b_dt)  (K=32) --------------
__global__ __launch_bounds__(256) void dt_kernel(
    const float* __restrict__ dbl, const float* __restrict__ Wdt,
    const float* __restrict__ bdt, float* __restrict__ dt)
{
    __shared__ float dtr[8][32];
    const int tid = threadIdx.x;
    const int row0 = blockIdx.x * 8;
    {
        int r = tid >> 5, c = tid & 31;
        dtr[r][c] = dbl[(size_t)(row0 + r) * DBLCOLS + c];
    }
    __syncthreads();

    const int base = tid * 4;
    float4 bb = *(const float4*)(bdt + base);
    float acc[8][4];
    #pragma unroll
    for (int r = 0; r < 8; r++) {
        acc[r][0] = bb.x; acc[r][1] = bb.y; acc[r][2] = bb.z; acc[r][3] = bb.w;
    }
    #pragma unroll
    for (int k = 0; k < 32; k++) {
        float4 w = *(const float4*)(Wdt + (size_t)k * DINNER + base);
        #pragma unroll
        for (int r = 0; r < 8; r++) {
            float a = dtr[r][k];
            acc[r][0] += a * w.x; acc[r][1] += a * w.y;
            acc[r][2] += a * w.z; acc[r][3] += a * w.w;
        }
    }
    #pragma unroll
    for (int r = 0; r < 8; r++) {
        float o[4];
        #pragma unroll
        for (int j = 0; j < 4; j++) {
            float v = acc[r][j];
            o[j] = (v > 20.f) ? v : log1pf(__expf(v));
        }
        *(float4*)(dt + (size_t)(row0 + r) * DINNER + base) =
            make_float4(o[0], o[1], o[2], o[3]);
    }
}

// ---------------- selective scan v3: 8 lanes/channel, 2 states/lane -----
#define SCH 8
#define ST  64
#define NCHUNK (LSEQ/ST)

struct ScanBuf {
    float dt[ST][SCH];
    float xc[ST][SCH];
    float zz[ST][SCH];
    float bc[ST][2*DSTATE];
};

__global__ __launch_bounds__(64) void scan_kernel(
    const float* __restrict__ xz, const float* __restrict__ xc,
    const float* __restrict__ dbl, const float* __restrict__ dt,
    const float* __restrict__ A_log, const float* __restrict__ Dp,
    uint32_t* __restrict__ ybf)
{
    __shared__ ScanBuf sb[2];
    __shared__ float sy[ST][SCH];

    const int tid  = threadIdx.x;          // 0..63
    const int lane = tid & 31;
    const int w    = tid >> 5;
    const int sg   = lane & 7;             // state group: states 2sg, 2sg+1
    const int cl   = w * 4 + (lane >> 3);  // local channel 0..7
    const int chb  = blockIdx.x * SCH;
    const int b    = chb >> 10;
    const int d0   = chb & (DINNER - 1);
    const int d    = d0 + cl;
    const size_t rowb = (size_t)b * LSEQ;

    const float A0 = -__expf(A_log[d * DSTATE + 2*sg    ]);
    const float A1 = -__expf(A_log[d * DSTATE + 2*sg + 1]);
    const float Dd = Dp[d];

    auto prefetch = [&](int c, int pp) {
        const size_t r0 = rowb + (size_t)c * ST;
        #pragma unroll
        for (int j = 0; j < 2; j++) {
            int u = tid + j * 64;
            int rw = u >> 1, qq = (u & 1) * 4;
            cp16(s2u(&sb[pp].dt[rw][qq]), dt + (r0 + rw) * DINNER + d0 + qq);
            cp16(s2u(&sb[pp].xc[rw][qq]), xc + (r0 + rw) * DINNER + d0 + qq);
            cp16(s2u(&sb[pp].zz[rw][qq]), xz + (r0 + rw) * XZCOLS + DINNER + d0 + qq);
        }
        #pragma unroll
        for (int j = 0; j < 8; j++) {
            int u = tid + j * 64;
            int rw = u >> 3, qq = (u & 7) * 4;
            cp16(s2u(&sb[pp].bc[rw][qq]), dbl + (r0 + rw) * DBLCOLS + DTRANK + qq);
        }
        asm volatile("cp.async.commit_group;\n" ::);
    };

    prefetch(0, 0);
    prefetch(1, 1);

    float h0 = 0.f, h1 = 0.f;
    for (int c = 0; c < NCHUNK; c++) {
        const int p = c & 1;
        if (c < NCHUNK - 1) asm volatile("cp.async.wait_group 1;\n" ::);
        else                asm volatile("cp.async.wait_group 0;\n" ::);
        __syncthreads();

        #pragma unroll 8
        for (int t = 0; t < ST; t++) {
            float dtv = sb[p].dt[t][cl];
            float xv  = sb[p].xc[t][cl];
            float2 Bv = *(const float2*)&sb[p].bc[t][2*sg];
            float2 Cv = *(const float2*)&sb[p].bc[t][DSTATE + 2*sg];
            float e0 = __expf(dtv * A0);
            float e1 = __expf(dtv * A1);
            float dx = dtv * xv;
            h0 = h0 * e0 + dx * Bv.x;
            h1 = h1 * e1 + dx * Bv.y;
            float pr = h0 * Cv.x + h1 * Cv.y;
            pr += __shfl_xor_sync(0xffffffffu, pr, 4);
            pr += __shfl_xor_sync(0xffffffffu, pr, 2);
            pr += __shfl_xor_sync(0xffffffffu, pr, 1);
            if (sg == 0) sy[t][cl] = pr + xv * Dd;
        }
        __syncthreads();

        float2 yv[4], zv[4];
        #pragma unroll
        for (int j = 0; j < 4; j++) {
            int u = tid + j * 64;
            int rw = u >> 2, p2 = (u & 3) * 2;
            yv[j] = *(const float2*)&sy[rw][p2];
            zv[j] = *(const float2*)&sb[p].zz[rw][p2];
        }
        __syncthreads();
        if (c + 2 < NCHUNK) prefetch(c + 2, p);

        const size_t r0 = rowb + (size_t)c * ST;
        #pragma unroll
        for (int j = 0; j < 4; j++) {
            int u = tid + j * 64;
            int rw = u >> 2, pi = (u & 3);
            float s0 = zv[j].x / (1.f + __expf(-zv[j].x));
            float s1 = zv[j].y / (1.f + __expf(-zv[j].y));
            ybf[(r0 + rw) * (DINNER/2) + (d0 >> 1) + pi] =
                pack_bf2(yv[j].x * s0, yv[j].y * s1);
        }
    }
}

// ---------------- residual + LayerNorm ----------------------------------
__global__ __launch_bounds__(128) void ln_kernel(
    const float* __restrict__ go, const float* __restrict__ x,
    const float* __restrict__ gamma, const float* __restrict__ beta,
    float* __restrict__ out)
{
    const int row = blockIdx.x;
    const int tid = threadIdx.x;
    float4 a  = *(const float4*)(go + (size_t)row * DMODEL + tid * 4);
    float4 xr = *(const float4*)(x  + (size_t)row * DMODEL + tid * 4);
    float v0 = a.x + xr.x, v1 = a.y + xr.y, v2 = a.z + xr.z, v3 = a.w + xr.w;

    float s  = v0 + v1 + v2 + v3;
    float sq = v0*v0 + v1*v1 + v2*v2 + v3*v3;
    #pragma unroll
    for (int o = 16; o > 0; o >>= 1) {
        s  += __shfl_xor_sync(0xffffffffu, s,  o);
        sq += __shfl_xor_sync(0xffffffffu, sq, o);
    }
    __shared__ float ss[4], ssq[4];
    if ((tid & 31) == 0) { ss[tid >> 5] = s; ssq[tid >> 5] = sq; }
    __syncthreads();
    s  = ss[0]  + ss[1]  + ss[2]  + ss[3];
    sq = ssq[0] + ssq[1] + ssq[2] + ssq[3];

    const float mu  = s * (1.f / DMODEL);
    const float var = sq * (1.f / DMODEL) - mu * mu;
    const float inv = rsqrtf(var + 1e-5f);

    float4 g  = *(const float4*)(gamma + tid * 4);
    float4 be = *(const float4*)(beta  + tid * 4);
    float4 o;
    o.x = (v0 - mu) * inv * g.x + be.x;
    o.y = (v1 - mu) * inv * g.y + be.y;
    o.z = (v2 - mu) * inv * g.z + be.z;
    o.w = (v3 - mu) * inv * g.w + be.w;
    *(float4*)(out + (size_t)row * DMODEL + tid * 4) = o;
}

// ---------------- launcher ----------------------------------------------
extern "C" void kernel_launch(void* const* d_in, const int* in_sizes, int n_in,
                              void* d_out, int out_size)
{
    (void)in_sizes; (void)n_in; (void)out_size;
    const float* x      = (const float*)d_in[0];
    const float* W_in   = (const float*)d_in[1];
    const float* conv_w = (const float*)d_in[2];
    const float* conv_b = (const float*)d_in[3];
    const float* W_xprj = (const float*)d_in[4];
    const float* W_dt   = (const float*)d_in[5];
    const float* b_dt   = (const float*)d_in[6];
    const float* A_log  = (const float*)d_in[7];
    const float* Dvec   = (const float*)d_in[8];
    const float* W_out  = (const float*)d_in[9];
    const float* gamma  = (const float*)d_in[10];
    const float* beta   = (const float*)d_in[11];
    float* out = (float*)d_out;

    float *p_xz, *p_xc, *p_dbl, *p_dt, *p_o;
    __nv_bfloat16* p_xcb;
    uint32_t *p_xb, *p_ybf, *p_wpin, *p_wpout, *p_wpx;
    cudaGetSymbolAddress((void**)&p_xz,    g_xz);
    cudaGetSymbolAddress((void**)&p_xc,    g_xc);
    cudaGetSymbolAddress((void**)&p_xcb,   g_xcb);
    cudaGetSymbolAddress((void**)&p_dbl,   g_dbl);
    cudaGetSymbolAddress((void**)&p_dt,    g_dt);
    cudaGetSymbolAddress((void**)&p_o,     g_o);
    cudaGetSymbolAddress((void**)&p_xb,    g_xb);
    cudaGetSymbolAddress((void**)&p_ybf,   g_ybf);
    cudaGetSymbolAddress((void**)&p_wpin,  g_wpin);
    cudaGetSymbolAddress((void**)&p_wpout, g_wpout);
    cudaGetSymbolAddress((void**)&p_wpx,   g_wpx);

    const int NCVT = NROWS*DMODEL/2 + (DMODEL/2)*XZCOLS + (DINNER/2)*DMODEL
                   + (DINNER/2)*DBLCOLS + NROWS*DBLCOLS/4;

    // 0) pack x / W_in / W_out / W_xproj to bf16 layouts + zero dbl
    cvt_pack_kernel<<<(NCVT + 255) / 256, 256>>>(x, W_in, W_out, W_xprj, p_xb,
                                                 p_wpin, p_wpout, p_wpx,
                                                 (float4*)p_dbl);
    // 1) xz = x @ W_in   (bf16 mma, pure cp.async operands)
    tmma_kernel<4><<<dim3(XZCOLS/128, NROWS/128), 256>>>(p_xb, p_wpin, p_xz, NROWS, XZCOLS, DMODEL);
    // 2) xc = silu(causal_conv(xi) + b)   (fp32 + bf16 outputs)
    conv_silu_kernel<<<((NROWS/4)*DINNER)/256, 256>>>(p_xz, conv_w, conv_b, p_xc, p_xcb);
    // 3) dbl += xc @ W_xproj   (bf16 mma, split-K x4, 256 CTAs)
    tmma_dbl_kernel<<<dim3(NROWS/64, 4), 256>>>((const uint32_t*)p_xcb, p_wpx, p_dbl);
    // 4) dt = softplus(dtr @ W_dt + b_dt)
    dt_kernel<<<NROWS/8, 256>>>(p_dbl, W_dt, b_dt, p_dt);
    // 5) selective scan (8 lanes/channel) -> y in bf16
    scan_kernel<<<(BATCH*DINNER)/SCH, 64>>>(p_xz, p_xc, p_dbl, p_dt, A_log, Dvec, p_ybf);
    // 6) o = y @ W_out   (bf16 mma, BM=64)
    tmma_kernel<2><<<dim3(DMODEL/128, NROWS/64), 256>>>(p_ybf, p_wpout, p_o, NROWS, DMODEL, DINNER);
    // 7) out = LN(o + x) * gamma + beta
    ln_kernel<<<NROWS, 128>>>(p_o, x, gamma, beta, out);
}